// round 2
// baseline (speedup 1.0000x reference)
#include <cuda_runtime.h>

#define BB 2
#define HH 16
#define NS 2048
#define HD 64
#define CD 1024
#define XSIZE (BB*NS*CD)
#define SCALE_F 0.125f

// Scratch (allocation-free rule: __device__ globals)
__device__ float g_qh[BB*HH*NS*HD];   // (B,H,N,hd)
__device__ float g_kh[BB*HH*NS*HD];
__device__ float g_vh[BB*HH*NS*HD];
__device__ float g_ao[BB*HH*NS*HD];   // attention output before proj

// ---------------------------------------------------------------------------
// Generic SGEMM: Y[m,j] = sum_k A[m,k] * W[j,k]   (A: M x K row-major or
// head-permuted gather; W: rows are output features, row-major; K = CD)
// BM=BN=128, BK=16, 256 threads, 8x8 per thread.
// ---------------------------------------------------------------------------
template<bool A_PERM, bool OUT_PERM, bool HAS_BIAS>
__global__ __launch_bounds__(256)
void sgemm_nt(const float* __restrict__ A, const float* __restrict__ W,
              float* __restrict__ Y, const float* __restrict__ bias)
{
    __shared__ float As[16][128];
    __shared__ float Ws[16][128];
    const int tid = threadIdx.x;
    const int tx = tid & 15, ty = tid >> 4;
    const int m0 = blockIdx.y * 128;
    const int n0 = blockIdx.x * 128;

    float acc[8][8];
#pragma unroll
    for (int i = 0; i < 8; i++)
#pragma unroll
        for (int j = 0; j < 8; j++) acc[i][j] = 0.f;

    for (int k0 = 0; k0 < CD; k0 += 16) {
#pragma unroll
        for (int v = 0; v < 2; v++) {
            int lin = tid + v * 256;
            int row = lin >> 2;
            int kc  = (lin & 3) << 2;
            int k   = k0 + kc;
            float4 av;
            if (A_PERM) {
                int m = m0 + row;
                int b = m / NS, n = m % NS;
                av = *(const float4*)(A + (((size_t)(b*HH + (k >> 6)) * NS + n) * HD + (k & 63)));
            } else {
                av = *(const float4*)(A + (size_t)(m0 + row) * CD + k);
            }
            As[kc+0][row] = av.x; As[kc+1][row] = av.y;
            As[kc+2][row] = av.z; As[kc+3][row] = av.w;
            float4 wv = *(const float4*)(W + (size_t)(n0 + row) * CD + k);
            Ws[kc+0][row] = wv.x; Ws[kc+1][row] = wv.y;
            Ws[kc+2][row] = wv.z; Ws[kc+3][row] = wv.w;
        }
        __syncthreads();
#pragma unroll
        for (int kk = 0; kk < 16; kk++) {
            float a[8], b[8];
            *(float4*)&a[0] = *(const float4*)&As[kk][ty*8];
            *(float4*)&a[4] = *(const float4*)&As[kk][ty*8 + 4];
            *(float4*)&b[0] = *(const float4*)&Ws[kk][tx*8];
            *(float4*)&b[4] = *(const float4*)&Ws[kk][tx*8 + 4];
#pragma unroll
            for (int i = 0; i < 8; i++)
#pragma unroll
                for (int j = 0; j < 8; j++)
                    acc[i][j] = fmaf(a[i], b[j], acc[i][j]);
        }
        __syncthreads();
    }

#pragma unroll
    for (int i = 0; i < 8; i++) {
        int m  = m0 + ty*8 + i;
        int b_ = m / NS, n = m % NS;
#pragma unroll
        for (int j4 = 0; j4 < 2; j4++) {
            int col = n0 + tx*8 + j4*4;
            float4 r;
            r.x = acc[i][j4*4+0]; r.y = acc[i][j4*4+1];
            r.z = acc[i][j4*4+2]; r.w = acc[i][j4*4+3];
            if (HAS_BIAS) {
                r.x += bias[col];   r.y += bias[col+1];
                r.z += bias[col+2]; r.w += bias[col+3];
            }
            float* yp;
            if (OUT_PERM)
                yp = Y + (((size_t)(b_*HH + (col >> 6)) * NS + n) * HD + (col & 63));
            else
                yp = Y + (size_t)m * CD + col;
            *(float4*)yp = r;
        }
    }
}

// ---------------------------------------------------------------------------
// Scores: P[bh, m, j] = scale * <Q[bh,m,:], K[bh,j,:]>, masked (j>m -> -1e9).
// Tiles strictly above the diagonal are short-circuited to -1e9 writes.
// BM=BN=128, K-dim = 64 done in two 32-chunks. 256 threads, 8x8 per thread.
// ---------------------------------------------------------------------------
__global__ __launch_bounds__(256)
void score_gemm(const float* __restrict__ Q, const float* __restrict__ Kh,
                float* __restrict__ P, const int* __restrict__ use_mask)
{
    const int bh = blockIdx.z;
    const int m0 = blockIdx.y * 128;
    const int j0 = blockIdx.x * 128;
    const int tid = threadIdx.x;
    const int tx = tid & 15, ty = tid >> 4;
    const bool masked = (*use_mask != 0);
    float* Pb = P + (size_t)bh * NS * NS;

    if (masked && j0 > m0 + 127) {
        const float4 neg = make_float4(-1e9f, -1e9f, -1e9f, -1e9f);
#pragma unroll
        for (int i = 0; i < 8; i++) {
            int m = m0 + ty*8 + i;
#pragma unroll
            for (int j4 = 0; j4 < 2; j4++)
                *(float4*)(Pb + (size_t)m * NS + j0 + tx*8 + j4*4) = neg;
        }
        return;
    }

    __shared__ float Qs[32][128];
    __shared__ float Ks[32][128];
    const float* Qb = Q  + (size_t)bh * NS * HD;
    const float* Kb = Kh + (size_t)bh * NS * HD;

    float acc[8][8];
#pragma unroll
    for (int i = 0; i < 8; i++)
#pragma unroll
        for (int j = 0; j < 8; j++) acc[i][j] = 0.f;

    for (int k0 = 0; k0 < HD; k0 += 32) {
#pragma unroll
        for (int v = 0; v < 4; v++) {
            int lin = tid + v * 256;
            int row = lin >> 3;
            int kc  = (lin & 7) << 2;
            float4 qv = *(const float4*)(Qb + (size_t)(m0 + row) * HD + k0 + kc);
            Qs[kc+0][row] = qv.x; Qs[kc+1][row] = qv.y;
            Qs[kc+2][row] = qv.z; Qs[kc+3][row] = qv.w;
            float4 kv = *(const float4*)(Kb + (size_t)(j0 + row) * HD + k0 + kc);
            Ks[kc+0][row] = kv.x; Ks[kc+1][row] = kv.y;
            Ks[kc+2][row] = kv.z; Ks[kc+3][row] = kv.w;
        }
        __syncthreads();
#pragma unroll
        for (int kk = 0; kk < 32; kk++) {
            float a[8], b[8];
            *(float4*)&a[0] = *(const float4*)&Qs[kk][ty*8];
            *(float4*)&a[4] = *(const float4*)&Qs[kk][ty*8 + 4];
            *(float4*)&b[0] = *(const float4*)&Ks[kk][tx*8];
            *(float4*)&b[4] = *(const float4*)&Ks[kk][tx*8 + 4];
#pragma unroll
            for (int i = 0; i < 8; i++)
#pragma unroll
                for (int j = 0; j < 8; j++)
                    acc[i][j] = fmaf(a[i], b[j], acc[i][j]);
        }
        __syncthreads();
    }

#pragma unroll
    for (int i = 0; i < 8; i++) {
        int m = m0 + ty*8 + i;
#pragma unroll
        for (int j4 = 0; j4 < 2; j4++) {
            int j = j0 + tx*8 + j4*4;
            float4 r;
            r.x = (masked && (j+0) > m) ? -1e9f : acc[i][j4*4+0] * SCALE_F;
            r.y = (masked && (j+1) > m) ? -1e9f : acc[i][j4*4+1] * SCALE_F;
            r.z = (masked && (j+2) > m) ? -1e9f : acc[i][j4*4+2] * SCALE_F;
            r.w = (masked && (j+3) > m) ? -1e9f : acc[i][j4*4+3] * SCALE_F;
            *(float4*)(Pb + (size_t)m * NS + j) = r;
        }
    }
}

// ---------------------------------------------------------------------------
// In-place row softmax over NS=2048 columns. One block per row; each thread
// holds 8 values in registers (2 float4), two shuffle+smem reductions.
// ---------------------------------------------------------------------------
__global__ __launch_bounds__(256)
void softmax_inplace(float* __restrict__ P)
{
    const size_t base = (size_t)blockIdx.x * NS;
    float4* p4 = (float4*)(P + base);
    const int tid = threadIdx.x;
    float4 v0 = p4[tid];
    float4 v1 = p4[tid + 256];

    float lmax = fmaxf(fmaxf(fmaxf(v0.x, v0.y), fmaxf(v0.z, v0.w)),
                       fmaxf(fmaxf(v1.x, v1.y), fmaxf(v1.z, v1.w)));
    __shared__ float red[8];
#pragma unroll
    for (int o = 16; o > 0; o >>= 1)
        lmax = fmaxf(lmax, __shfl_xor_sync(0xffffffffu, lmax, o));
    if ((tid & 31) == 0) red[tid >> 5] = lmax;
    __syncthreads();
    float bmax = red[0];
#pragma unroll
    for (int w = 1; w < 8; w++) bmax = fmaxf(bmax, red[w]);

    v0.x = __expf(v0.x - bmax); v0.y = __expf(v0.y - bmax);
    v0.z = __expf(v0.z - bmax); v0.w = __expf(v0.w - bmax);
    v1.x = __expf(v1.x - bmax); v1.y = __expf(v1.y - bmax);
    v1.z = __expf(v1.z - bmax); v1.w = __expf(v1.w - bmax);
    float lsum = v0.x + v0.y + v0.z + v0.w + v1.x + v1.y + v1.z + v1.w;
#pragma unroll
    for (int o = 16; o > 0; o >>= 1)
        lsum += __shfl_xor_sync(0xffffffffu, lsum, o);
    __syncthreads();                 // red reuse
    if ((tid & 31) == 0) red[tid >> 5] = lsum;
    __syncthreads();
    float bsum = 0.f;
#pragma unroll
    for (int w = 0; w < 8; w++) bsum += red[w];
    const float inv = 1.f / bsum;

    v0.x *= inv; v0.y *= inv; v0.z *= inv; v0.w *= inv;
    v1.x *= inv; v1.y *= inv; v1.z *= inv; v1.w *= inv;
    p4[tid] = v0;
    p4[tid + 256] = v1;
}

// ---------------------------------------------------------------------------
// O[bh, m, :] = P[bh, m, :] @ V[bh, :, :]   (P: NSxNS, V: NSx64)
// BM=128 rows, full 64 cols, BK=32. Causal: truncate k-range (P is 0 beyond).
// ---------------------------------------------------------------------------
__global__ __launch_bounds__(256)
void av_gemm(const float* __restrict__ P, const float* __restrict__ V,
             float* __restrict__ O, const int* __restrict__ use_mask)
{
    const int bh = blockIdx.y;
    const int m0 = blockIdx.x * 128;
    const int tid = threadIdx.x;
    const int tx = tid & 15, ty = tid >> 4;
    const bool masked = (*use_mask != 0);
    const int kmax = masked ? (m0 + 128) : NS;

    __shared__ float Ps[32][128];
    __shared__ float Vs[32][64];
    const float* Pb = P + (size_t)bh * NS * NS;
    const float* Vb = V + (size_t)bh * NS * HD;

    float acc[8][4];
#pragma unroll
    for (int i = 0; i < 8; i++)
#pragma unroll
        for (int j = 0; j < 4; j++) acc[i][j] = 0.f;

    for (int kk0 = 0; kk0 < kmax; kk0 += 32) {
#pragma unroll
        for (int v = 0; v < 4; v++) {
            int lin = tid + v * 256;
            int row = lin >> 3;
            int kc  = (lin & 7) << 2;
            float4 pv = *(const float4*)(Pb + (size_t)(m0 + row) * NS + kk0 + kc);
            Ps[kc+0][row] = pv.x; Ps[kc+1][row] = pv.y;
            Ps[kc+2][row] = pv.z; Ps[kc+3][row] = pv.w;
        }
#pragma unroll
        for (int v = 0; v < 2; v++) {
            int lin = tid + v * 256;
            int r = lin >> 4;
            int c = (lin & 15) << 2;
            *(float4*)&Vs[r][c] = *(const float4*)(Vb + (size_t)(kk0 + r) * HD + c);
        }
        __syncthreads();
#pragma unroll
        for (int kk = 0; kk < 32; kk++) {
            float a[8], b[4];
            *(float4*)&a[0] = *(const float4*)&Ps[kk][ty*8];
            *(float4*)&a[4] = *(const float4*)&Ps[kk][ty*8 + 4];
            *(float4*)&b[0] = *(const float4*)&Vs[kk][tx*4];
#pragma unroll
            for (int i = 0; i < 8; i++)
#pragma unroll
                for (int j = 0; j < 4; j++)
                    acc[i][j] = fmaf(a[i], b[j], acc[i][j]);
        }
        __syncthreads();
    }

#pragma unroll
    for (int i = 0; i < 8; i++) {
        int m = m0 + ty*8 + i;
        float4 r;
        r.x = acc[i][0]; r.y = acc[i][1]; r.z = acc[i][2]; r.w = acc[i][3];
        *(float4*)(O + ((size_t)bh * NS + m) * HD + tx*4) = r;
    }
}

// ---------------------------------------------------------------------------
extern "C" void kernel_launch(void* const* d_in, const int* in_sizes, int n_in,
                              void* d_out, int out_size)
{
    const float* q      = (const float*)d_in[0];
    const float* k      = (const float*)d_in[1];
    const float* v      = (const float*)d_in[2];
    const float* qkv_w  = (const float*)d_in[3];
    const float* proj_w = (const float*)d_in[4];
    const float* proj_b = (const float*)d_in[5];
    const int*   use_mask = (const int*)d_in[6];

    float* out      = (float*)d_out;
    float* x_out    = out;                       // (B, N, C)
    float* attn_out = out + (size_t)XSIZE;       // (B, H, N, N)

    float *qh, *kh, *vh, *ao;
    cudaGetSymbolAddress((void**)&qh, g_qh);
    cudaGetSymbolAddress((void**)&kh, g_kh);
    cudaGetSymbolAddress((void**)&vh, g_vh);
    cudaGetSymbolAddress((void**)&ao, g_ao);

    dim3 blk(256);
    dim3 gproj(CD / 128, (BB * NS) / 128);       // (8, 32)

    // QKV projections (write head-transposed layouts)
    sgemm_nt<false, true, false><<<gproj, blk>>>(q, qkv_w,                qh, nullptr);
    sgemm_nt<false, true, false><<<gproj, blk>>>(k, qkv_w + CD*CD,        kh, nullptr);
    sgemm_nt<false, true, false><<<gproj, blk>>>(v, qkv_w + 2*(size_t)CD*CD, vh, nullptr);

    // Scaled masked scores -> attn_out (raw)
    score_gemm<<<dim3(NS/128, NS/128, BB*HH), blk>>>(qh, kh, attn_out, use_mask);

    // Row softmax in place (this IS the second output)
    softmax_inplace<<<BB*HH*NS, blk>>>(attn_out);

    // attn @ V -> head-layout output
    av_gemm<<<dim3(NS/128, BB*HH), blk>>>(attn_out, vh, ao, use_mask);

    // Output projection + bias (gathers head layout)
    sgemm_nt<true, false, true><<<gproj, blk>>>(ao, proj_w, x_out, proj_b);
}

// round 5
// speedup vs baseline: 1.0705x; 1.0705x over previous
#include <cuda_runtime.h>

#define BB 2
#define HH 16
#define NS 2048
#define HD 64
#define CD 1024
#define XSIZE (BB*NS*CD)
#define SCALE_F 0.125f
#define HSZ (BB*HH*NS*HD)

// Scratch (allocation-free rule: __device__ globals)
__device__ float g_qh[HSZ];              // (B,H,N,hd)
__device__ float g_kh[HSZ];
__device__ float g_vh[HSZ];
__device__ float g_ao[HSZ];              // attention output before proj
__device__ float g_partial[BB*HH*NS*16]; // per-(row, j-block) exp partial sums
__device__ float g_inv[BB*HH*NS];        // 1 / row sum

// ---------------------------------------------------------------------------
// QKV projection: Y[z][m,j] = sum_k A_z[m,k] * W_z[j,k], head-permuted output.
// z = blockIdx.z selects q/k/v. BM=BN=128, BK=16, 256 thr, 8x8/thread.
// ---------------------------------------------------------------------------
__global__ __launch_bounds__(256)
void sgemm_qkv(const float* __restrict__ Aq, const float* __restrict__ Ak,
               const float* __restrict__ Av, const float* __restrict__ Wall,
               float* __restrict__ Yq, float* __restrict__ Yk,
               float* __restrict__ Yv)
{
    __shared__ float As[16][128];
    __shared__ float Ws[16][128];
    const int z = blockIdx.z;
    const float* A = (z == 0) ? Aq : (z == 1) ? Ak : Av;
    const float* W = Wall + (size_t)z * CD * CD;
    float* Y = (z == 0) ? Yq : (z == 1) ? Yk : Yv;

    const int tid = threadIdx.x;
    const int tx = tid & 15, ty = tid >> 4;
    const int m0 = blockIdx.y * 128;
    const int n0 = blockIdx.x * 128;

    float acc[8][8];
#pragma unroll
    for (int i = 0; i < 8; i++)
#pragma unroll
        for (int j = 0; j < 8; j++) acc[i][j] = 0.f;

    for (int k0 = 0; k0 < CD; k0 += 16) {
#pragma unroll
        for (int v = 0; v < 2; v++) {
            int lin = tid + v * 256;
            int row = lin >> 2;
            int kc  = (lin & 3) << 2;
            int k   = k0 + kc;
            float4 av = *(const float4*)(A + (size_t)(m0 + row) * CD + k);
            As[kc+0][row] = av.x; As[kc+1][row] = av.y;
            As[kc+2][row] = av.z; As[kc+3][row] = av.w;
            float4 wv = *(const float4*)(W + (size_t)(n0 + row) * CD + k);
            Ws[kc+0][row] = wv.x; Ws[kc+1][row] = wv.y;
            Ws[kc+2][row] = wv.z; Ws[kc+3][row] = wv.w;
        }
        __syncthreads();
#pragma unroll
        for (int kk = 0; kk < 16; kk++) {
            float a[8], b[8];
            *(float4*)&a[0] = *(const float4*)&As[kk][ty*8];
            *(float4*)&a[4] = *(const float4*)&As[kk][ty*8 + 4];
            *(float4*)&b[0] = *(const float4*)&Ws[kk][tx*8];
            *(float4*)&b[4] = *(const float4*)&Ws[kk][tx*8 + 4];
#pragma unroll
            for (int i = 0; i < 8; i++)
#pragma unroll
                for (int j = 0; j < 8; j++)
                    acc[i][j] = fmaf(a[i], b[j], acc[i][j]);
        }
        __syncthreads();
    }

#pragma unroll
    for (int i = 0; i < 8; i++) {
        int m  = m0 + ty*8 + i;
        int b_ = m / NS, n = m % NS;
#pragma unroll
        for (int j4 = 0; j4 < 2; j4++) {
            int col = n0 + tx*8 + j4*4;
            float4 r;
            r.x = acc[i][j4*4+0]; r.y = acc[i][j4*4+1];
            r.z = acc[i][j4*4+2]; r.w = acc[i][j4*4+3];
            *(float4*)(Y + (((size_t)(b_*HH + (col >> 6)) * NS + n) * HD + (col & 63))) = r;
        }
    }
}

// ---------------------------------------------------------------------------
// Output projection with head-layout gather + bias.
// ---------------------------------------------------------------------------
__global__ __launch_bounds__(256)
void sgemm_proj(const float* __restrict__ A, const float* __restrict__ W,
                float* __restrict__ Y, const float* __restrict__ bias)
{
    __shared__ float As[16][128];
    __shared__ float Ws[16][128];
    const int tid = threadIdx.x;
    const int tx = tid & 15, ty = tid >> 4;
    const int m0 = blockIdx.y * 128;
    const int n0 = blockIdx.x * 128;

    float acc[8][8];
#pragma unroll
    for (int i = 0; i < 8; i++)
#pragma unroll
        for (int j = 0; j < 8; j++) acc[i][j] = 0.f;

    for (int k0 = 0; k0 < CD; k0 += 16) {
#pragma unroll
        for (int v = 0; v < 2; v++) {
            int lin = tid + v * 256;
            int row = lin >> 2;
            int kc  = (lin & 3) << 2;
            int k   = k0 + kc;
            int m = m0 + row;
            int b = m / NS, n = m % NS;
            float4 av = *(const float4*)(A + (((size_t)(b*HH + (k >> 6)) * NS + n) * HD + (k & 63)));
            As[kc+0][row] = av.x; As[kc+1][row] = av.y;
            As[kc+2][row] = av.z; As[kc+3][row] = av.w;
            float4 wv = *(const float4*)(W + (size_t)(n0 + row) * CD + k);
            Ws[kc+0][row] = wv.x; Ws[kc+1][row] = wv.y;
            Ws[kc+2][row] = wv.z; Ws[kc+3][row] = wv.w;
        }
        __syncthreads();
#pragma unroll
        for (int kk = 0; kk < 16; kk++) {
            float a[8], b[8];
            *(float4*)&a[0] = *(const float4*)&As[kk][ty*8];
            *(float4*)&a[4] = *(const float4*)&As[kk][ty*8 + 4];
            *(float4*)&b[0] = *(const float4*)&Ws[kk][tx*8];
            *(float4*)&b[4] = *(const float4*)&Ws[kk][tx*8 + 4];
#pragma unroll
            for (int i = 0; i < 8; i++)
#pragma unroll
                for (int j = 0; j < 8; j++)
                    acc[i][j] = fmaf(a[i], b[j], acc[i][j]);
        }
        __syncthreads();
    }

#pragma unroll
    for (int i = 0; i < 8; i++) {
        int m = m0 + ty*8 + i;
#pragma unroll
        for (int j4 = 0; j4 < 2; j4++) {
            int col = n0 + tx*8 + j4*4;
            float4 r;
            r.x = acc[i][j4*4+0] + bias[col];
            r.y = acc[i][j4*4+1] + bias[col+1];
            r.z = acc[i][j4*4+2] + bias[col+2];
            r.w = acc[i][j4*4+3] + bias[col+3];
            *(float4*)(Y + (size_t)m * CD + col) = r;
        }
    }
}

// ---------------------------------------------------------------------------
// Scores -> exp(scale*dot) (masked -> 0), plus per-(row, j-block) partial sums.
// Tiles strictly above the diagonal short-circuit to 0 writes + 0 partials.
// ---------------------------------------------------------------------------
__global__ __launch_bounds__(256)
void score_exp_gemm(const float* __restrict__ Q, const float* __restrict__ Kh,
                    float* __restrict__ P, float* __restrict__ partial,
                    const int* __restrict__ use_mask)
{
    const int bh = blockIdx.z;
    const int m0 = blockIdx.y * 128;
    const int j0 = blockIdx.x * 128;
    const int jblk = blockIdx.x;
    const int tid = threadIdx.x;
    const int tx = tid & 15, ty = tid >> 4;
    const bool masked = (*use_mask != 0);
    float* Pb = P + (size_t)bh * NS * NS;

    if (masked && j0 > m0 + 127) {
        const float4 zer = make_float4(0.f, 0.f, 0.f, 0.f);
#pragma unroll
        for (int i = 0; i < 8; i++) {
            int m = m0 + ty*8 + i;
#pragma unroll
            for (int j4 = 0; j4 < 2; j4++)
                *(float4*)(Pb + (size_t)m * NS + j0 + tx*8 + j4*4) = zer;
        }
        if (tid < 128)
            partial[((size_t)bh * NS + m0 + tid) * 16 + jblk] = 0.f;
        return;
    }

    __shared__ float Qs[32][128];
    __shared__ float Ks[32][128];
    const float* Qb = Q  + (size_t)bh * NS * HD;
    const float* Kb = Kh + (size_t)bh * NS * HD;

    float acc[8][8];
#pragma unroll
    for (int i = 0; i < 8; i++)
#pragma unroll
        for (int j = 0; j < 8; j++) acc[i][j] = 0.f;

    for (int k0 = 0; k0 < HD; k0 += 32) {
#pragma unroll
        for (int v = 0; v < 4; v++) {
            int lin = tid + v * 256;
            int row = lin >> 3;
            int kc  = (lin & 7) << 2;
            float4 qv = *(const float4*)(Qb + (size_t)(m0 + row) * HD + k0 + kc);
            Qs[kc+0][row] = qv.x; Qs[kc+1][row] = qv.y;
            Qs[kc+2][row] = qv.z; Qs[kc+3][row] = qv.w;
            float4 kv = *(const float4*)(Kb + (size_t)(j0 + row) * HD + k0 + kc);
            Ks[kc+0][row] = kv.x; Ks[kc+1][row] = kv.y;
            Ks[kc+2][row] = kv.z; Ks[kc+3][row] = kv.w;
        }
        __syncthreads();
#pragma unroll
        for (int kk = 0; kk < 32; kk++) {
            float a[8], b[8];
            *(float4*)&a[0] = *(const float4*)&Qs[kk][ty*8];
            *(float4*)&a[4] = *(const float4*)&Qs[kk][ty*8 + 4];
            *(float4*)&b[0] = *(const float4*)&Ks[kk][tx*8];
            *(float4*)&b[4] = *(const float4*)&Ks[kk][tx*8 + 4];
#pragma unroll
            for (int i = 0; i < 8; i++)
#pragma unroll
                for (int j = 0; j < 8; j++)
                    acc[i][j] = fmaf(a[i], b[j], acc[i][j]);
        }
        __syncthreads();
    }

    // Epilogue: exp + write + per-row partial sums (reuse Qs as scratch)
    __syncthreads();
    float* Srow = &Qs[0][0];          // 128 rows x 16 cols, padded stride 17
#pragma unroll
    for (int i = 0; i < 8; i++) {
        int m = m0 + ty*8 + i;
        float rs = 0.f;
#pragma unroll
        for (int j4 = 0; j4 < 2; j4++) {
            int j = j0 + tx*8 + j4*4;
            float4 r;
            r.x = (masked && (j+0) > m) ? 0.f : __expf(acc[i][j4*4+0] * SCALE_F);
            r.y = (masked && (j+1) > m) ? 0.f : __expf(acc[i][j4*4+1] * SCALE_F);
            r.z = (masked && (j+2) > m) ? 0.f : __expf(acc[i][j4*4+2] * SCALE_F);
            r.w = (masked && (j+3) > m) ? 0.f : __expf(acc[i][j4*4+3] * SCALE_F);
            rs += r.x + r.y + r.z + r.w;
            *(float4*)(Pb + (size_t)m * NS + j) = r;
        }
        Srow[(ty*8 + i) * 17 + tx] = rs;
    }
    __syncthreads();
    if (tid < 128) {
        float s = 0.f;
#pragma unroll
        for (int t = 0; t < 16; t++) s += Srow[tid * 17 + t];
        partial[((size_t)bh * NS + m0 + tid) * 16 + jblk] = s;
    }
}

// ---------------------------------------------------------------------------
// Reduce 16 partials/row -> inverse row sum.
// ---------------------------------------------------------------------------
__global__ __launch_bounds__(256)
void rowinv(const float* __restrict__ partial, float* __restrict__ inv)
{
    int r = blockIdx.x * 256 + threadIdx.x;   // 0 .. BB*HH*NS-1
    const float4* p = (const float4*)(partial + (size_t)r * 16);
    float4 a = p[0], b = p[1], c = p[2], d = p[3];
    float s = (a.x + a.y + a.z + a.w) + (b.x + b.y + b.z + b.w)
            + (c.x + c.y + c.z + c.w) + (d.x + d.y + d.z + d.w);
    inv[r] = 1.f / s;
}

// ---------------------------------------------------------------------------
// O = softmax(P) @ V. Loads exp-P, scales by inv[row], writes normalized P
// back (finalizing the attn output), accumulates O. Causal: k-range truncated
// (above-diagonal region is already exactly 0 from score_exp_gemm).
// ---------------------------------------------------------------------------
__global__ __launch_bounds__(256)
void av_gemm(float* __restrict__ P, const float* __restrict__ V,
             float* __restrict__ O, const float* __restrict__ inv,
             const int* __restrict__ use_mask)
{
    const int bh = blockIdx.y;
    const int m0 = blockIdx.x * 128;
    const int tid = threadIdx.x;
    const int tx = tid & 15, ty = tid >> 4;
    const bool masked = (*use_mask != 0);
    const int kmax = masked ? (m0 + 128) : NS;

    __shared__ float Ps[32][128];
    __shared__ float Vs[32][64];
    __shared__ float sinv[128];
    float* Pb = P + (size_t)bh * NS * NS;
    const float* Vb = V + (size_t)bh * NS * HD;

    if (tid < 128) sinv[tid] = inv[(size_t)bh * NS + m0 + tid];
    __syncthreads();

    float acc[8][4];
#pragma unroll
    for (int i = 0; i < 8; i++)
#pragma unroll
        for (int j = 0; j < 4; j++) acc[i][j] = 0.f;

    for (int kk0 = 0; kk0 < kmax; kk0 += 32) {
#pragma unroll
        for (int v = 0; v < 4; v++) {
            int lin = tid + v * 256;
            int row = lin >> 3;
            int kc  = (lin & 7) << 2;
            float* pp = Pb + (size_t)(m0 + row) * NS + kk0 + kc;
            float4 pv = *(const float4*)pp;
            float iv = sinv[row];
            pv.x *= iv; pv.y *= iv; pv.z *= iv; pv.w *= iv;
            *(float4*)pp = pv;                       // finalize attn output
            Ps[kc+0][row] = pv.x; Ps[kc+1][row] = pv.y;
            Ps[kc+2][row] = pv.z; Ps[kc+3][row] = pv.w;
        }
#pragma unroll
        for (int v = 0; v < 2; v++) {
            int lin = tid + v * 256;
            int r = lin >> 4;
            int c = (lin & 15) << 2;
            *(float4*)&Vs[r][c] = *(const float4*)(Vb + (size_t)(kk0 + r) * HD + c);
        }
        __syncthreads();
#pragma unroll
        for (int kk = 0; kk < 32; kk++) {
            float a[8], b[4];
            *(float4*)&a[0] = *(const float4*)&Ps[kk][ty*8];
            *(float4*)&a[4] = *(const float4*)&Ps[kk][ty*8 + 4];
            *(float4*)&b[0] = *(const float4*)&Vs[kk][tx*4];
#pragma unroll
            for (int i = 0; i < 8; i++)
#pragma unroll
                for (int j = 0; j < 4; j++)
                    acc[i][j] = fmaf(a[i], b[j], acc[i][j]);
        }
        __syncthreads();
    }

#pragma unroll
    for (int i = 0; i < 8; i++) {
        int m = m0 + ty*8 + i;
        float4 r;
        r.x = acc[i][0]; r.y = acc[i][1]; r.z = acc[i][2]; r.w = acc[i][3];
        *(float4*)(O + ((size_t)bh * NS + m) * HD + tx*4) = r;
    }
}

// ---------------------------------------------------------------------------
extern "C" void kernel_launch(void* const* d_in, const int* in_sizes, int n_in,
                              void* d_out, int out_size)
{
    const float* q      = (const float*)d_in[0];
    const float* k      = (const float*)d_in[1];
    const float* v      = (const float*)d_in[2];
    const float* qkv_w  = (const float*)d_in[3];
    const float* proj_w = (const float*)d_in[4];
    const float* proj_b = (const float*)d_in[5];
    const int*   use_mask = (const int*)d_in[6];

    float* out      = (float*)d_out;
    float* x_out    = out;                       // (B, N, C)
    float* attn_out = out + (size_t)XSIZE;       // (B, H, N, N)

    float *qh, *kh, *vh, *ao, *part, *invs;
    cudaGetSymbolAddress((void**)&qh, g_qh);
    cudaGetSymbolAddress((void**)&kh, g_kh);
    cudaGetSymbolAddress((void**)&vh, g_vh);
    cudaGetSymbolAddress((void**)&ao, g_ao);
    cudaGetSymbolAddress((void**)&part, g_partial);
    cudaGetSymbolAddress((void**)&invs, g_inv);

    dim3 blk(256);

    // Fused QKV projections (head-transposed outputs), one launch
    sgemm_qkv<<<dim3(CD/128, (BB*NS)/128, 3), blk>>>(q, k, v, qkv_w, qh, kh, vh);

    // exp(scale * Q K^T) with mask -> attn_out (unnormalized) + partial sums
    score_exp_gemm<<<dim3(NS/128, NS/128, BB*HH), blk>>>(qh, kh, attn_out, part, use_mask);

    // Row inverse sums
    rowinv<<<(BB*HH*NS)/256, blk>>>(part, invs);

    // Normalize P (finalizing attn output) + P @ V
    av_gemm<<<dim3(NS/128, BB*HH), blk>>>(attn_out, vh, ao, invs, use_mask);

    // Output projection + bias
    sgemm_proj<<<dim3(CD/128, (BB*NS)/128), blk>>>(ao, proj_w, x_out, proj_b);
}

// round 8
// speedup vs baseline: 1.1061x; 1.0333x over previous
#include <cuda_runtime.h>

#define BB 2
#define HH 16
#define NS 2048
#define HD 64
#define CD 1024
#define XSIZE (BB*NS*CD)
#define SCALE_F 0.125f
#define HSZ (BB*HH*NS*HD)

// Scratch (allocation-free rule: __device__ globals)
__device__ float g_qh[HSZ];              // (B,H,N,hd)
__device__ float g_kh[HSZ];
__device__ float g_vh[HSZ];
__device__ float g_ao[HSZ];              // attention output before proj
__device__ float g_partial[BB*HH*NS*16]; // per-(row, j-block) exp partial sums
__device__ float g_inv[BB*HH*NS];        // 1 / row sum

// ---------------------------------------------------------------------------
// QKV projection, double-buffered. Y[z][m,j] = sum_k A_z[m,k]*W_z[j,k],
// head-permuted output. BM=BN=128, BK=16, 256 thr, 8x8/thread.
// ---------------------------------------------------------------------------
__global__ __launch_bounds__(256)
void sgemm_qkv(const float* __restrict__ Aq, const float* __restrict__ Ak,
               const float* __restrict__ Av, const float* __restrict__ Wall,
               float* __restrict__ Yq, float* __restrict__ Yk,
               float* __restrict__ Yv)
{
    __shared__ float As[2][16][128];
    __shared__ float Ws[2][16][128];
    const int z = blockIdx.z;
    const float* A = (z == 0) ? Aq : (z == 1) ? Ak : Av;
    const float* W = Wall + (size_t)z * CD * CD;
    float* Y = (z == 0) ? Yq : (z == 1) ? Yk : Yv;

    const int tid = threadIdx.x;
    const int tx = tid & 15, ty = tid >> 4;
    const int m0 = blockIdx.y * 128;
    const int n0 = blockIdx.x * 128;

    const int r0  = tid >> 2;            // rows 0..63
    const int r1  = r0 + 64;             // rows 64..127
    const int kc0 = (tid & 3) << 2;

    float4 sa0, sa1, sw0, sw1;
    // prologue: tile 0
    sa0 = *(const float4*)(A + (size_t)(m0 + r0) * CD + kc0);
    sw0 = *(const float4*)(W + (size_t)(n0 + r0) * CD + kc0);
    sa1 = *(const float4*)(A + (size_t)(m0 + r1) * CD + kc0);
    sw1 = *(const float4*)(W + (size_t)(n0 + r1) * CD + kc0);
    As[0][kc0+0][r0] = sa0.x; As[0][kc0+1][r0] = sa0.y;
    As[0][kc0+2][r0] = sa0.z; As[0][kc0+3][r0] = sa0.w;
    Ws[0][kc0+0][r0] = sw0.x; Ws[0][kc0+1][r0] = sw0.y;
    Ws[0][kc0+2][r0] = sw0.z; Ws[0][kc0+3][r0] = sw0.w;
    As[0][kc0+0][r1] = sa1.x; As[0][kc0+1][r1] = sa1.y;
    As[0][kc0+2][r1] = sa1.z; As[0][kc0+3][r1] = sa1.w;
    Ws[0][kc0+0][r1] = sw1.x; Ws[0][kc0+1][r1] = sw1.y;
    Ws[0][kc0+2][r1] = sw1.z; Ws[0][kc0+3][r1] = sw1.w;

    float acc[8][8];
#pragma unroll
    for (int i = 0; i < 8; i++)
#pragma unroll
        for (int j = 0; j < 8; j++) acc[i][j] = 0.f;

    const int NT = CD / 16;
    for (int t = 0; t < NT; t++) {
        __syncthreads();
        if (t + 1 < NT) {
            int k = (t + 1) * 16 + kc0;
            sa0 = *(const float4*)(A + (size_t)(m0 + r0) * CD + k);
            sw0 = *(const float4*)(W + (size_t)(n0 + r0) * CD + k);
            sa1 = *(const float4*)(A + (size_t)(m0 + r1) * CD + k);
            sw1 = *(const float4*)(W + (size_t)(n0 + r1) * CD + k);
        }
        const int cb = t & 1;
#pragma unroll
        for (int kk = 0; kk < 16; kk++) {
            float a[8], b[8];
            *(float4*)&a[0] = *(const float4*)&As[cb][kk][ty*8];
            *(float4*)&a[4] = *(const float4*)&As[cb][kk][ty*8 + 4];
            *(float4*)&b[0] = *(const float4*)&Ws[cb][kk][tx*8];
            *(float4*)&b[4] = *(const float4*)&Ws[cb][kk][tx*8 + 4];
#pragma unroll
            for (int i = 0; i < 8; i++)
#pragma unroll
                for (int j = 0; j < 8; j++)
                    acc[i][j] = fmaf(a[i], b[j], acc[i][j]);
        }
        if (t + 1 < NT) {
            const int nb = (t + 1) & 1;
            As[nb][kc0+0][r0] = sa0.x; As[nb][kc0+1][r0] = sa0.y;
            As[nb][kc0+2][r0] = sa0.z; As[nb][kc0+3][r0] = sa0.w;
            Ws[nb][kc0+0][r0] = sw0.x; Ws[nb][kc0+1][r0] = sw0.y;
            Ws[nb][kc0+2][r0] = sw0.z; Ws[nb][kc0+3][r0] = sw0.w;
            As[nb][kc0+0][r1] = sa1.x; As[nb][kc0+1][r1] = sa1.y;
            As[nb][kc0+2][r1] = sa1.z; As[nb][kc0+3][r1] = sa1.w;
            Ws[nb][kc0+0][r1] = sw1.x; Ws[nb][kc0+1][r1] = sw1.y;
            Ws[nb][kc0+2][r1] = sw1.z; Ws[nb][kc0+3][r1] = sw1.w;
        }
    }

#pragma unroll
    for (int i = 0; i < 8; i++) {
        int m  = m0 + ty*8 + i;
        int b_ = m / NS, n = m % NS;
#pragma unroll
        for (int j4 = 0; j4 < 2; j4++) {
            int col = n0 + tx*8 + j4*4;
            float4 r;
            r.x = acc[i][j4*4+0]; r.y = acc[i][j4*4+1];
            r.z = acc[i][j4*4+2]; r.w = acc[i][j4*4+3];
            *(float4*)(Y + (((size_t)(b_*HH + (col >> 6)) * NS + n) * HD + (col & 63))) = r;
        }
    }
}

// ---------------------------------------------------------------------------
// Output projection, double-buffered, head-layout gather + bias.
// ---------------------------------------------------------------------------
__global__ __launch_bounds__(256)
void sgemm_proj(const float* __restrict__ A, const float* __restrict__ W,
                float* __restrict__ Y, const float* __restrict__ bias)
{
    __shared__ float As[2][16][128];
    __shared__ float Ws[2][16][128];
    const int tid = threadIdx.x;
    const int tx = tid & 15, ty = tid >> 4;
    const int m0 = blockIdx.y * 128;
    const int n0 = blockIdx.x * 128;

    const int r0  = tid >> 2;
    const int r1  = r0 + 64;
    const int kc0 = (tid & 3) << 2;
    // Gather coords for permuted A: row -> (b, n)
    const int mm0 = m0 + r0, b0 = mm0 / NS, n0r = mm0 % NS;
    const int mm1 = m0 + r1, b1 = mm1 / NS, n1r = mm1 % NS;

    float4 sa0, sa1, sw0, sw1;
    sa0 = *(const float4*)(A + (((size_t)(b0*HH + (kc0 >> 6)) * NS + n0r) * HD + (kc0 & 63)));
    sw0 = *(const float4*)(W + (size_t)(n0 + r0) * CD + kc0);
    sa1 = *(const float4*)(A + (((size_t)(b1*HH + (kc0 >> 6)) * NS + n1r) * HD + (kc0 & 63)));
    sw1 = *(const float4*)(W + (size_t)(n0 + r1) * CD + kc0);
    As[0][kc0+0][r0] = sa0.x; As[0][kc0+1][r0] = sa0.y;
    As[0][kc0+2][r0] = sa0.z; As[0][kc0+3][r0] = sa0.w;
    Ws[0][kc0+0][r0] = sw0.x; Ws[0][kc0+1][r0] = sw0.y;
    Ws[0][kc0+2][r0] = sw0.z; Ws[0][kc0+3][r0] = sw0.w;
    As[0][kc0+0][r1] = sa1.x; As[0][kc0+1][r1] = sa1.y;
    As[0][kc0+2][r1] = sa1.z; As[0][kc0+3][r1] = sa1.w;
    Ws[0][kc0+0][r1] = sw1.x; Ws[0][kc0+1][r1] = sw1.y;
    Ws[0][kc0+2][r1] = sw1.z; Ws[0][kc0+3][r1] = sw1.w;

    float acc[8][8];
#pragma unroll
    for (int i = 0; i < 8; i++)
#pragma unroll
        for (int j = 0; j < 8; j++) acc[i][j] = 0.f;

    const int NT = CD / 16;
    for (int t = 0; t < NT; t++) {
        __syncthreads();
        if (t + 1 < NT) {
            int k = (t + 1) * 16 + kc0;
            sa0 = *(const float4*)(A + (((size_t)(b0*HH + (k >> 6)) * NS + n0r) * HD + (k & 63)));
            sw0 = *(const float4*)(W + (size_t)(n0 + r0) * CD + k);
            sa1 = *(const float4*)(A + (((size_t)(b1*HH + (k >> 6)) * NS + n1r) * HD + (k & 63)));
            sw1 = *(const float4*)(W + (size_t)(n0 + r1) * CD + k);
        }
        const int cb = t & 1;
#pragma unroll
        for (int kk = 0; kk < 16; kk++) {
            float a[8], b[8];
            *(float4*)&a[0] = *(const float4*)&As[cb][kk][ty*8];
            *(float4*)&a[4] = *(const float4*)&As[cb][kk][ty*8 + 4];
            *(float4*)&b[0] = *(const float4*)&Ws[cb][kk][tx*8];
            *(float4*)&b[4] = *(const float4*)&Ws[cb][kk][tx*8 + 4];
#pragma unroll
            for (int i = 0; i < 8; i++)
#pragma unroll
                for (int j = 0; j < 8; j++)
                    acc[i][j] = fmaf(a[i], b[j], acc[i][j]);
        }
        if (t + 1 < NT) {
            const int nb = (t + 1) & 1;
            As[nb][kc0+0][r0] = sa0.x; As[nb][kc0+1][r0] = sa0.y;
            As[nb][kc0+2][r0] = sa0.z; As[nb][kc0+3][r0] = sa0.w;
            Ws[nb][kc0+0][r0] = sw0.x; Ws[nb][kc0+1][r0] = sw0.y;
            Ws[nb][kc0+2][r0] = sw0.z; Ws[nb][kc0+3][r0] = sw0.w;
            As[nb][kc0+0][r1] = sa1.x; As[nb][kc0+1][r1] = sa1.y;
            As[nb][kc0+2][r1] = sa1.z; As[nb][kc0+3][r1] = sa1.w;
            Ws[nb][kc0+0][r1] = sw1.x; Ws[nb][kc0+1][r1] = sw1.y;
            Ws[nb][kc0+2][r1] = sw1.z; Ws[nb][kc0+3][r1] = sw1.w;
        }
    }

#pragma unroll
    for (int i = 0; i < 8; i++) {
        int m = m0 + ty*8 + i;
#pragma unroll
        for (int j4 = 0; j4 < 2; j4++) {
            int col = n0 + tx*8 + j4*4;
            float4 r;
            r.x = acc[i][j4*4+0] + bias[col];
            r.y = acc[i][j4*4+1] + bias[col+1];
            r.z = acc[i][j4*4+2] + bias[col+2];
            r.w = acc[i][j4*4+3] + bias[col+3];
            *(float4*)(Y + (size_t)m * CD + col) = r;
        }
    }
}

// ---------------------------------------------------------------------------
// Scores -> exp(scale*dot) (masked -> 0), plus per-(row, j-block) partial sums.
// Tiles strictly above the diagonal short-circuit to 0 writes + 0 partials.
// ---------------------------------------------------------------------------
__global__ __launch_bounds__(256)
void score_exp_gemm(const float* __restrict__ Q, const float* __restrict__ Kh,
                    float* __restrict__ P, float* __restrict__ partial,
                    const int* __restrict__ use_mask)
{
    const int bh = blockIdx.z;
    const int m0 = blockIdx.y * 128;
    const int j0 = blockIdx.x * 128;
    const int jblk = blockIdx.x;
    const int tid = threadIdx.x;
    const int tx = tid & 15, ty = tid >> 4;
    const bool masked = (*use_mask != 0);
    float* Pb = P + (size_t)bh * NS * NS;

    if (masked && j0 > m0 + 127) {
        const float4 zer = make_float4(0.f, 0.f, 0.f, 0.f);
#pragma unroll
        for (int i = 0; i < 8; i++) {
            int m = m0 + ty*8 + i;
#pragma unroll
            for (int j4 = 0; j4 < 2; j4++)
                *(float4*)(Pb + (size_t)m * NS + j0 + tx*8 + j4*4) = zer;
        }
        if (tid < 128)
            partial[((size_t)bh * NS + m0 + tid) * 16 + jblk] = 0.f;
        return;
    }

    __shared__ float Qs[32][128];
    __shared__ float Ks[32][128];
    const float* Qb = Q  + (size_t)bh * NS * HD;
    const float* Kb = Kh + (size_t)bh * NS * HD;

    float acc[8][8];
#pragma unroll
    for (int i = 0; i < 8; i++)
#pragma unroll
        for (int j = 0; j < 8; j++) acc[i][j] = 0.f;

    for (int k0 = 0; k0 < HD; k0 += 32) {
#pragma unroll
        for (int v = 0; v < 4; v++) {
            int lin = tid + v * 256;
            int row = lin >> 3;
            int kc  = (lin & 7) << 2;
            float4 qv = *(const float4*)(Qb + (size_t)(m0 + row) * HD + k0 + kc);
            Qs[kc+0][row] = qv.x; Qs[kc+1][row] = qv.y;
            Qs[kc+2][row] = qv.z; Qs[kc+3][row] = qv.w;
            float4 kv = *(const float4*)(Kb + (size_t)(j0 + row) * HD + k0 + kc);
            Ks[kc+0][row] = kv.x; Ks[kc+1][row] = kv.y;
            Ks[kc+2][row] = kv.z; Ks[kc+3][row] = kv.w;
        }
        __syncthreads();
#pragma unroll
        for (int kk = 0; kk < 32; kk++) {
            float a[8], b[8];
            *(float4*)&a[0] = *(const float4*)&Qs[kk][ty*8];
            *(float4*)&a[4] = *(const float4*)&Qs[kk][ty*8 + 4];
            *(float4*)&b[0] = *(const float4*)&Ks[kk][tx*8];
            *(float4*)&b[4] = *(const float4*)&Ks[kk][tx*8 + 4];
#pragma unroll
            for (int i = 0; i < 8; i++)
#pragma unroll
                for (int j = 0; j < 8; j++)
                    acc[i][j] = fmaf(a[i], b[j], acc[i][j]);
        }
        __syncthreads();
    }

    // Epilogue: exp + write + per-row partial sums (reuse Qs as scratch)
    __syncthreads();
    float* Srow = &Qs[0][0];          // 128 rows x 16 cols, padded stride 17
#pragma unroll
    for (int i = 0; i < 8; i++) {
        int m = m0 + ty*8 + i;
        float rs = 0.f;
#pragma unroll
        for (int j4 = 0; j4 < 2; j4++) {
            int j = j0 + tx*8 + j4*4;
            float4 r;
            r.x = (masked && (j+0) > m) ? 0.f : __expf(acc[i][j4*4+0] * SCALE_F);
            r.y = (masked && (j+1) > m) ? 0.f : __expf(acc[i][j4*4+1] * SCALE_F);
            r.z = (masked && (j+2) > m) ? 0.f : __expf(acc[i][j4*4+2] * SCALE_F);
            r.w = (masked && (j+3) > m) ? 0.f : __expf(acc[i][j4*4+3] * SCALE_F);
            rs += r.x + r.y + r.z + r.w;
            *(float4*)(Pb + (size_t)m * NS + j) = r;
        }
        Srow[(ty*8 + i) * 17 + tx] = rs;
    }
    __syncthreads();
    if (tid < 128) {
        float s = 0.f;
#pragma unroll
        for (int t = 0; t < 16; t++) s += Srow[tid * 17 + t];
        partial[((size_t)bh * NS + m0 + tid) * 16 + jblk] = s;
    }
}

// ---------------------------------------------------------------------------
// Reduce 16 partials/row -> inverse row sum.
// ---------------------------------------------------------------------------
__global__ __launch_bounds__(256)
void rowinv(const float* __restrict__ partial, float* __restrict__ inv)
{
    int r = blockIdx.x * 256 + threadIdx.x;   // 0 .. BB*HH*NS-1
    const float4* p = (const float4*)(partial + (size_t)r * 16);
    float4 a = p[0], b = p[1], c = p[2], d = p[3];
    float s = (a.x + a.y + a.z + a.w) + (b.x + b.y + b.z + b.w)
            + (c.x + c.y + c.z + c.w) + (d.x + d.y + d.z + d.w);
    inv[r] = 1.f / s;
}

// ---------------------------------------------------------------------------
// O = softmax(P) @ V, double-buffered. GEMM runs on RAW exp-P; the sinv scale
// is factored into the O epilogue (exact: O = sinv[m] * sum_k Praw*V).
// Normalized P written back from staged registers in the STS step.
// Heavy (large m0) CTAs launch first via reversed blockIdx.x.
// ---------------------------------------------------------------------------
__global__ __launch_bounds__(256)
void av_gemm(float* __restrict__ P, const float* __restrict__ V,
             float* __restrict__ O, const float* __restrict__ inv,
             const int* __restrict__ use_mask)
{
    const int bh = blockIdx.y;
    const int m0 = ((int)gridDim.x - 1 - (int)blockIdx.x) * 128;
    const int tid = threadIdx.x;
    const int tx = tid & 15, ty = tid >> 4;
    const bool masked = (*use_mask != 0);
    const int kmax = masked ? (m0 + 128) : NS;
    const int NT = kmax >> 5;

    __shared__ float Ps[2][32][128];
    __shared__ float Vs[2][32][64];
    __shared__ float sinv_s[128];

    float* Pb = P + (size_t)bh * NS * NS;
    const float* Vb = V + (size_t)bh * NS * HD;

    if (tid < 128) sinv_s[tid] = inv[(size_t)bh * NS + m0 + tid];

    const int pr0 = tid >> 3;            // rows 0..31
    const int pr1 = pr0 + 32;
    const int pr2 = pr0 + 64;
    const int pr3 = pr0 + 96;
    const int pkc = (tid & 7) << 2;
    const int vr0 = tid >> 4;            // 0..15
    const int vr1 = vr0 + 16;
    const int vc  = (tid & 15) << 2;

    float4 sp0, sp1, sp2, sp3, sv0, sv1;
    // prologue: tile 0
    {
        sp0 = *(const float4*)(Pb + (size_t)(m0 + pr0) * NS + pkc);
        sp1 = *(const float4*)(Pb + (size_t)(m0 + pr1) * NS + pkc);
        sp2 = *(const float4*)(Pb + (size_t)(m0 + pr2) * NS + pkc);
        sp3 = *(const float4*)(Pb + (size_t)(m0 + pr3) * NS + pkc);
        sv0 = *(const float4*)(Vb + (size_t)vr0 * HD + vc);
        sv1 = *(const float4*)(Vb + (size_t)vr1 * HD + vc);
    }
    __syncthreads();                     // sinv_s visible
    // sts tile 0 (+ normalized write-back)
    {
        Ps[0][pkc+0][pr0] = sp0.x; Ps[0][pkc+1][pr0] = sp0.y;
        Ps[0][pkc+2][pr0] = sp0.z; Ps[0][pkc+3][pr0] = sp0.w;
        Ps[0][pkc+0][pr1] = sp1.x; Ps[0][pkc+1][pr1] = sp1.y;
        Ps[0][pkc+2][pr1] = sp1.z; Ps[0][pkc+3][pr1] = sp1.w;
        Ps[0][pkc+0][pr2] = sp2.x; Ps[0][pkc+1][pr2] = sp2.y;
        Ps[0][pkc+2][pr2] = sp2.z; Ps[0][pkc+3][pr2] = sp2.w;
        Ps[0][pkc+0][pr3] = sp3.x; Ps[0][pkc+1][pr3] = sp3.y;
        Ps[0][pkc+2][pr3] = sp3.z; Ps[0][pkc+3][pr3] = sp3.w;
        *(float4*)&Vs[0][vr0][vc] = sv0;
        *(float4*)&Vs[0][vr1][vc] = sv1;
        float s0 = sinv_s[pr0], s1 = sinv_s[pr1], s2 = sinv_s[pr2], s3 = sinv_s[pr3];
        float4 w;
        w.x = sp0.x*s0; w.y = sp0.y*s0; w.z = sp0.z*s0; w.w = sp0.w*s0;
        *(float4*)(Pb + (size_t)(m0 + pr0) * NS + pkc) = w;
        w.x = sp1.x*s1; w.y = sp1.y*s1; w.z = sp1.z*s1; w.w = sp1.w*s1;
        *(float4*)(Pb + (size_t)(m0 + pr1) * NS + pkc) = w;
        w.x = sp2.x*s2; w.y = sp2.y*s2; w.z = sp2.z*s2; w.w = sp2.w*s2;
        *(float4*)(Pb + (size_t)(m0 + pr2) * NS + pkc) = w;
        w.x = sp3.x*s3; w.y = sp3.y*s3; w.z = sp3.z*s3; w.w = sp3.w*s3;
        *(float4*)(Pb + (size_t)(m0 + pr3) * NS + pkc) = w;
    }

    float acc[8][4];
#pragma unroll
    for (int i = 0; i < 8; i++)
#pragma unroll
        for (int j = 0; j < 4; j++) acc[i][j] = 0.f;

    for (int t = 0; t < NT; t++) {
        __syncthreads();
        if (t + 1 < NT) {
            int kk0 = (t + 1) * 32;
            sp0 = *(const float4*)(Pb + (size_t)(m0 + pr0) * NS + kk0 + pkc);
            sp1 = *(const float4*)(Pb + (size_t)(m0 + pr1) * NS + kk0 + pkc);
            sp2 = *(const float4*)(Pb + (size_t)(m0 + pr2) * NS + kk0 + pkc);
            sp3 = *(const float4*)(Pb + (size_t)(m0 + pr3) * NS + kk0 + pkc);
            sv0 = *(const float4*)(Vb + (size_t)(kk0 + vr0) * HD + vc);
            sv1 = *(const float4*)(Vb + (size_t)(kk0 + vr1) * HD + vc);
        }
        const int cb = t & 1;
#pragma unroll
        for (int kk = 0; kk < 32; kk++) {
            float a[8], b[4];
            *(float4*)&a[0] = *(const float4*)&Ps[cb][kk][ty*8];
            *(float4*)&a[4] = *(const float4*)&Ps[cb][kk][ty*8 + 4];
            *(float4*)&b[0] = *(const float4*)&Vs[cb][kk][tx*4];
#pragma unroll
            for (int i = 0; i < 8; i++)
#pragma unroll
                for (int j = 0; j < 4; j++)
                    acc[i][j] = fmaf(a[i], b[j], acc[i][j]);
        }
        if (t + 1 < NT) {
            const int nb = (t + 1) & 1;
            const int kk0 = (t + 1) * 32;
            Ps[nb][pkc+0][pr0] = sp0.x; Ps[nb][pkc+1][pr0] = sp0.y;
            Ps[nb][pkc+2][pr0] = sp0.z; Ps[nb][pkc+3][pr0] = sp0.w;
            Ps[nb][pkc+0][pr1] = sp1.x; Ps[nb][pkc+1][pr1] = sp1.y;
            Ps[nb][pkc+2][pr1] = sp1.z; Ps[nb][pkc+3][pr1] = sp1.w;
            Ps[nb][pkc+0][pr2] = sp2.x; Ps[nb][pkc+1][pr2] = sp2.y;
            Ps[nb][pkc+2][pr2] = sp2.z; Ps[nb][pkc+3][pr2] = sp2.w;
            Ps[nb][pkc+0][pr3] = sp3.x; Ps[nb][pkc+1][pr3] = sp3.y;
            Ps[nb][pkc+2][pr3] = sp3.z; Ps[nb][pkc+3][pr3] = sp3.w;
            *(float4*)&Vs[nb][vr0][vc] = sv0;
            *(float4*)&Vs[nb][vr1][vc] = sv1;
            float s0 = sinv_s[pr0], s1 = sinv_s[pr1], s2 = sinv_s[pr2], s3 = sinv_s[pr3];
            float4 w;
            w.x = sp0.x*s0; w.y = sp0.y*s0; w.z = sp0.z*s0; w.w = sp0.w*s0;
            *(float4*)(Pb + (size_t)(m0 + pr0) * NS + kk0 + pkc) = w;
            w.x = sp1.x*s1; w.y = sp1.y*s1; w.z = sp1.z*s1; w.w = sp1.w*s1;
            *(float4*)(Pb + (size_t)(m0 + pr1) * NS + kk0 + pkc) = w;
            w.x = sp2.x*s2; w.y = sp2.y*s2; w.z = sp2.z*s2; w.w = sp2.w*s2;
            *(float4*)(Pb + (size_t)(m0 + pr2) * NS + kk0 + pkc) = w;
            w.x = sp3.x*s3; w.y = sp3.y*s3; w.z = sp3.z*s3; w.w = sp3.w*s3;
            *(float4*)(Pb + (size_t)(m0 + pr3) * NS + kk0 + pkc) = w;
        }
    }

#pragma unroll
    for (int i = 0; i < 8; i++) {
        int m = m0 + ty*8 + i;
        float si = sinv_s[ty*8 + i];
        float4 r;
        r.x = acc[i][0]*si; r.y = acc[i][1]*si;
        r.z = acc[i][2]*si; r.w = acc[i][3]*si;
        *(float4*)(O + ((size_t)bh * NS + m) * HD + tx*4) = r;
    }
}

// ---------------------------------------------------------------------------
extern "C" void kernel_launch(void* const* d_in, const int* in_sizes, int n_in,
                              void* d_out, int out_size)
{
    const float* q      = (const float*)d_in[0];
    const float* k      = (const float*)d_in[1];
    const float* v      = (const float*)d_in[2];
    const float* qkv_w  = (const float*)d_in[3];
    const float* proj_w = (const float*)d_in[4];
    const float* proj_b = (const float*)d_in[5];
    const int*   use_mask = (const int*)d_in[6];

    float* out      = (float*)d_out;
    float* x_out    = out;                       // (B, N, C)
    float* attn_out = out + (size_t)XSIZE;       // (B, H, N, N)

    float *qh, *kh, *vh, *ao, *part, *invs;
    cudaGetSymbolAddress((void**)&qh, g_qh);
    cudaGetSymbolAddress((void**)&kh, g_kh);
    cudaGetSymbolAddress((void**)&vh, g_vh);
    cudaGetSymbolAddress((void**)&ao, g_ao);
    cudaGetSymbolAddress((void**)&part, g_partial);
    cudaGetSymbolAddress((void**)&invs, g_inv);

    dim3 blk(256);

    // Fused QKV projections (head-transposed outputs), one launch
    sgemm_qkv<<<dim3(CD/128, (BB*NS)/128, 3), blk>>>(q, k, v, qkv_w, qh, kh, vh);

    // exp(scale * Q K^T) with mask -> attn_out (unnormalized) + partial sums
    score_exp_gemm<<<dim3(NS/128, NS/128, BB*HH), blk>>>(qh, kh, attn_out, part, use_mask);

    // Row inverse sums
    rowinv<<<(BB*HH*NS)/256, blk>>>(part, invs);

    // Normalize P (finalizing attn output) + P @ V
    av_gemm<<<dim3(NS/128, BB*HH), blk>>>(attn_out, vh, ao, invs, use_mask);

    // Output projection + bias
    sgemm_proj<<<dim3(CD/128, (BB*NS)/128), blk>>>(ao, proj_w, x_out, proj_b);
}

// round 10
// speedup vs baseline: 1.5718x; 1.4210x over previous
#include <cuda_runtime.h>
#include <cstdint>

#define BB 2
#define HH 16
#define NS 2048
#define HD 64
#define CD 1024
#define XSIZE (BB*NS*CD)
#define SCALE_F 0.125f
#define HSZ (BB*HH*NS*HD)

// Scratch (allocation-free rule: __device__ globals)
__device__ float g_qh[HSZ];              // (B,H,N,hd)
__device__ float g_kh[HSZ];
__device__ float g_vh[HSZ];
__device__ float g_ao[HSZ];              // attention output before proj
__device__ float g_partial[BB*HH*NS*16]; // per-(row, j-block) exp partial sums
__device__ float g_inv[BB*HH*NS];        // 1 / row sum

__device__ __forceinline__ uint32_t f2tf32(float x) {
    uint32_t y; asm("cvt.rna.tf32.f32 %0, %1;" : "=r"(y) : "f"(x)); return y;
}
__device__ __forceinline__ void mma_tf32(float& d0, float& d1, float& d2, float& d3,
                                         uint32_t a0, uint32_t a1, uint32_t a2, uint32_t a3,
                                         uint32_t b0, uint32_t b1) {
    asm volatile(
        "mma.sync.aligned.m16n8k8.row.col.f32.tf32.tf32.f32 "
        "{%0,%1,%2,%3}, {%4,%5,%6,%7}, {%8,%9}, {%0,%1,%2,%3};"
        : "+f"(d0), "+f"(d1), "+f"(d2), "+f"(d3)
        : "r"(a0), "r"(a1), "r"(a2), "r"(a3), "r"(b0), "r"(b1));
}

// ---------------------------------------------------------------------------
// TF32 mma.sync GEMM: Y[m,j] = sum_k A[m,k] * W[j,k].  256 thr = 8 warps
// (2 m x 4 n), warp tile 64x32, BM=BN=128, BK=16 (2 mma k-steps).
// MODE 0: qkv (A row-major, Y head-permuted).  MODE 1: proj (A head-gather,
// Y row-major + bias).
// ---------------------------------------------------------------------------
template<int MODE>
__global__ __launch_bounds__(256)
void mma_mm(const float* __restrict__ Aq, const float* __restrict__ Ak,
            const float* __restrict__ Av, const float* __restrict__ Wall,
            float* __restrict__ Yq, float* __restrict__ Yk,
            float* __restrict__ Yv, const float* __restrict__ bias)
{
    __shared__ uint32_t As[2][16][132];
    __shared__ uint32_t Bs[2][16][132];

    const int tid  = threadIdx.x;
    const int lane = tid & 31;
    const int warp = tid >> 5;
    const int wm = warp >> 2;            // 0..1
    const int wn = warp & 3;             // 0..3
    const int m0 = blockIdx.y * 128;
    const int n0 = blockIdx.x * 128;

    const float* A;
    const float* W;
    float* Y;
    if (MODE == 0) {
        const int z = blockIdx.z;
        A = (z == 0) ? Aq : (z == 1) ? Ak : Av;
        W = Wall + (size_t)z * CD * CD;
        Y = (z == 0) ? Yq : (z == 1) ? Yk : Yv;
    } else {
        A = Aq; W = Wall; Y = Yq;
    }

    // global->smem staging geometry (2 rows x float4 per thread, as in R8)
    const int r0  = tid >> 2;            // 0..63
    const int r1  = r0 + 64;
    const int kc0 = (tid & 3) << 2;

    // proj gather coords
    int gb0 = 0, gn0 = 0, gb1 = 0, gn1 = 0;
    if (MODE == 1) {
        int mm0 = m0 + r0; gb0 = mm0 >> 11; gn0 = mm0 & (NS - 1);
        int mm1 = m0 + r1; gb1 = mm1 >> 11; gn1 = mm1 & (NS - 1);
    }

    float4 sa0, sa1, sw0, sw1;
    // prologue: tile 0
    if (MODE == 0) {
        sa0 = *(const float4*)(A + (size_t)(m0 + r0) * CD + kc0);
        sa1 = *(const float4*)(A + (size_t)(m0 + r1) * CD + kc0);
    } else {
        sa0 = *(const float4*)(A + (((size_t)(gb0*HH + (kc0 >> 6)) * NS + gn0) * HD + (kc0 & 63)));
        sa1 = *(const float4*)(A + (((size_t)(gb1*HH + (kc0 >> 6)) * NS + gn1) * HD + (kc0 & 63)));
    }
    sw0 = *(const float4*)(W + (size_t)(n0 + r0) * CD + kc0);
    sw1 = *(const float4*)(W + (size_t)(n0 + r1) * CD + kc0);
    As[0][kc0+0][r0] = f2tf32(sa0.x); As[0][kc0+1][r0] = f2tf32(sa0.y);
    As[0][kc0+2][r0] = f2tf32(sa0.z); As[0][kc0+3][r0] = f2tf32(sa0.w);
    As[0][kc0+0][r1] = f2tf32(sa1.x); As[0][kc0+1][r1] = f2tf32(sa1.y);
    As[0][kc0+2][r1] = f2tf32(sa1.z); As[0][kc0+3][r1] = f2tf32(sa1.w);
    Bs[0][kc0+0][r0] = f2tf32(sw0.x); Bs[0][kc0+1][r0] = f2tf32(sw0.y);
    Bs[0][kc0+2][r0] = f2tf32(sw0.z); Bs[0][kc0+3][r0] = f2tf32(sw0.w);
    Bs[0][kc0+0][r1] = f2tf32(sw1.x); Bs[0][kc0+1][r1] = f2tf32(sw1.y);
    Bs[0][kc0+2][r1] = f2tf32(sw1.z); Bs[0][kc0+3][r1] = f2tf32(sw1.w);

    float acc[4][4][4];
#pragma unroll
    for (int i = 0; i < 4; i++)
#pragma unroll
        for (int j = 0; j < 4; j++)
#pragma unroll
            for (int c = 0; c < 4; c++) acc[i][j][c] = 0.f;

    const int lq = lane & 3;             // k offset within fragment
    const int lr = lane >> 2;            // row/col offset within fragment

    const int NT = CD / 16;
    for (int t = 0; t < NT; t++) {
        __syncthreads();
        if (t + 1 < NT) {
            int k = (t + 1) * 16 + kc0;
            if (MODE == 0) {
                sa0 = *(const float4*)(A + (size_t)(m0 + r0) * CD + k);
                sa1 = *(const float4*)(A + (size_t)(m0 + r1) * CD + k);
            } else {
                sa0 = *(const float4*)(A + (((size_t)(gb0*HH + (k >> 6)) * NS + gn0) * HD + (k & 63)));
                sa1 = *(const float4*)(A + (((size_t)(gb1*HH + (k >> 6)) * NS + gn1) * HD + (k & 63)));
            }
            sw0 = *(const float4*)(W + (size_t)(n0 + r0) * CD + k);
            sw1 = *(const float4*)(W + (size_t)(n0 + r1) * CD + k);
        }
        const int cb = t & 1;
#pragma unroll
        for (int ks = 0; ks < 2; ks++) {
            const int kb = ks * 8;
            uint32_t af[4][4], bf[4][2];
#pragma unroll
            for (int i = 0; i < 4; i++) {
                int m = wm * 64 + i * 16 + lr;
                af[i][0] = As[cb][kb + lq    ][m];
                af[i][1] = As[cb][kb + lq    ][m + 8];
                af[i][2] = As[cb][kb + lq + 4][m];
                af[i][3] = As[cb][kb + lq + 4][m + 8];
            }
#pragma unroll
            for (int j = 0; j < 4; j++) {
                int n = wn * 32 + j * 8 + lr;
                bf[j][0] = Bs[cb][kb + lq    ][n];
                bf[j][1] = Bs[cb][kb + lq + 4][n];
            }
#pragma unroll
            for (int i = 0; i < 4; i++)
#pragma unroll
                for (int j = 0; j < 4; j++)
                    mma_tf32(acc[i][j][0], acc[i][j][1], acc[i][j][2], acc[i][j][3],
                             af[i][0], af[i][1], af[i][2], af[i][3],
                             bf[j][0], bf[j][1]);
        }
        if (t + 1 < NT) {
            const int nb = (t + 1) & 1;
            As[nb][kc0+0][r0] = f2tf32(sa0.x); As[nb][kc0+1][r0] = f2tf32(sa0.y);
            As[nb][kc0+2][r0] = f2tf32(sa0.z); As[nb][kc0+3][r0] = f2tf32(sa0.w);
            As[nb][kc0+0][r1] = f2tf32(sa1.x); As[nb][kc0+1][r1] = f2tf32(sa1.y);
            As[nb][kc0+2][r1] = f2tf32(sa1.z); As[nb][kc0+3][r1] = f2tf32(sa1.w);
            Bs[nb][kc0+0][r0] = f2tf32(sw0.x); Bs[nb][kc0+1][r0] = f2tf32(sw0.y);
            Bs[nb][kc0+2][r0] = f2tf32(sw0.z); Bs[nb][kc0+3][r0] = f2tf32(sw0.w);
            Bs[nb][kc0+0][r1] = f2tf32(sw1.x); Bs[nb][kc0+1][r1] = f2tf32(sw1.y);
            Bs[nb][kc0+2][r1] = f2tf32(sw1.z); Bs[nb][kc0+3][r1] = f2tf32(sw1.w);
        }
    }

    // Epilogue: direct register->global stores (float2 per c-pair)
#pragma unroll
    for (int i = 0; i < 4; i++) {
#pragma unroll
        for (int j = 0; j < 4; j++) {
            int col = n0 + wn * 32 + j * 8 + 2 * lq;
            int mA = m0 + wm * 64 + i * 16 + lr;
            int mB = mA + 8;
            float2 v0, v1;
            v0.x = acc[i][j][0]; v0.y = acc[i][j][1];
            v1.x = acc[i][j][2]; v1.y = acc[i][j][3];
            if (MODE == 0) {
                int bA = mA >> 11, nA = mA & (NS - 1);
                int bB = mB >> 11, nB = mB & (NS - 1);
                int head = col >> 6, off = col & 63;
                *(float2*)(Y + (((size_t)(bA*HH + head) * NS + nA) * HD + off)) = v0;
                *(float2*)(Y + (((size_t)(bB*HH + head) * NS + nB) * HD + off)) = v1;
            } else {
                float bx = bias[col], by = bias[col + 1];
                v0.x += bx; v0.y += by;
                v1.x += bx; v1.y += by;
                *(float2*)(Y + (size_t)mA * CD + col) = v0;
                *(float2*)(Y + (size_t)mB * CD + col) = v1;
            }
        }
    }
}

// ---------------------------------------------------------------------------
// Scores -> exp(scale*dot) (masked -> 0), plus per-(row, j-block) partial sums.
// ---------------------------------------------------------------------------
__global__ __launch_bounds__(256)
void score_exp_gemm(const float* __restrict__ Q, const float* __restrict__ Kh,
                    float* __restrict__ P, float* __restrict__ partial,
                    const int* __restrict__ use_mask)
{
    const int bh = blockIdx.z;
    const int m0 = blockIdx.y * 128;
    const int j0 = blockIdx.x * 128;
    const int jblk = blockIdx.x;
    const int tid = threadIdx.x;
    const int tx = tid & 15, ty = tid >> 4;
    const bool masked = (*use_mask != 0);
    float* Pb = P + (size_t)bh * NS * NS;

    if (masked && j0 > m0 + 127) {
        const float4 zer = make_float4(0.f, 0.f, 0.f, 0.f);
#pragma unroll
        for (int i = 0; i < 8; i++) {
            int m = m0 + ty*8 + i;
#pragma unroll
            for (int j4 = 0; j4 < 2; j4++)
                *(float4*)(Pb + (size_t)m * NS + j0 + tx*8 + j4*4) = zer;
        }
        if (tid < 128)
            partial[((size_t)bh * NS + m0 + tid) * 16 + jblk] = 0.f;
        return;
    }

    __shared__ float Qs[32][128];
    __shared__ float Ks[32][128];
    const float* Qb = Q  + (size_t)bh * NS * HD;
    const float* Kb = Kh + (size_t)bh * NS * HD;

    float acc[8][8];
#pragma unroll
    for (int i = 0; i < 8; i++)
#pragma unroll
        for (int j = 0; j < 8; j++) acc[i][j] = 0.f;

    for (int k0 = 0; k0 < HD; k0 += 32) {
#pragma unroll
        for (int v = 0; v < 4; v++) {
            int lin = tid + v * 256;
            int row = lin >> 3;
            int kc  = (lin & 7) << 2;
            float4 qv = *(const float4*)(Qb + (size_t)(m0 + row) * HD + k0 + kc);
            Qs[kc+0][row] = qv.x; Qs[kc+1][row] = qv.y;
            Qs[kc+2][row] = qv.z; Qs[kc+3][row] = qv.w;
            float4 kv = *(const float4*)(Kb + (size_t)(j0 + row) * HD + k0 + kc);
            Ks[kc+0][row] = kv.x; Ks[kc+1][row] = kv.y;
            Ks[kc+2][row] = kv.z; Ks[kc+3][row] = kv.w;
        }
        __syncthreads();
#pragma unroll
        for (int kk = 0; kk < 32; kk++) {
            float a[8], b[8];
            *(float4*)&a[0] = *(const float4*)&Qs[kk][ty*8];
            *(float4*)&a[4] = *(const float4*)&Qs[kk][ty*8 + 4];
            *(float4*)&b[0] = *(const float4*)&Ks[kk][tx*8];
            *(float4*)&b[4] = *(const float4*)&Ks[kk][tx*8 + 4];
#pragma unroll
            for (int i = 0; i < 8; i++)
#pragma unroll
                for (int j = 0; j < 8; j++)
                    acc[i][j] = fmaf(a[i], b[j], acc[i][j]);
        }
        __syncthreads();
    }

    __syncthreads();
    float* Srow = &Qs[0][0];          // 128 x 16, stride 17
#pragma unroll
    for (int i = 0; i < 8; i++) {
        int m = m0 + ty*8 + i;
        float rs = 0.f;
#pragma unroll
        for (int j4 = 0; j4 < 2; j4++) {
            int j = j0 + tx*8 + j4*4;
            float4 r;
            r.x = (masked && (j+0) > m) ? 0.f : __expf(acc[i][j4*4+0] * SCALE_F);
            r.y = (masked && (j+1) > m) ? 0.f : __expf(acc[i][j4*4+1] * SCALE_F);
            r.z = (masked && (j+2) > m) ? 0.f : __expf(acc[i][j4*4+2] * SCALE_F);
            r.w = (masked && (j+3) > m) ? 0.f : __expf(acc[i][j4*4+3] * SCALE_F);
            rs += r.x + r.y + r.z + r.w;
            *(float4*)(Pb + (size_t)m * NS + j) = r;
        }
        Srow[(ty*8 + i) * 17 + tx] = rs;
    }
    __syncthreads();
    if (tid < 128) {
        float s = 0.f;
#pragma unroll
        for (int t = 0; t < 16; t++) s += Srow[tid * 17 + t];
        partial[((size_t)bh * NS + m0 + tid) * 16 + jblk] = s;
    }
}

// ---------------------------------------------------------------------------
__global__ __launch_bounds__(256)
void rowinv(const float* __restrict__ partial, float* __restrict__ inv)
{
    int r = blockIdx.x * 256 + threadIdx.x;
    const float4* p = (const float4*)(partial + (size_t)r * 16);
    float4 a = p[0], b = p[1], c = p[2], d = p[3];
    float s = (a.x + a.y + a.z + a.w) + (b.x + b.y + b.z + b.w)
            + (c.x + c.y + c.z + c.w) + (d.x + d.y + d.z + d.w);
    inv[r] = 1.f / s;
}

// ---------------------------------------------------------------------------
// O = softmax(P) @ V, double-buffered (unchanged from R8 best).
// ---------------------------------------------------------------------------
__global__ __launch_bounds__(256)
void av_gemm(float* __restrict__ P, const float* __restrict__ V,
             float* __restrict__ O, const float* __restrict__ inv,
             const int* __restrict__ use_mask)
{
    const int bh = blockIdx.y;
    const int m0 = ((int)gridDim.x - 1 - (int)blockIdx.x) * 128;
    const int tid = threadIdx.x;
    const int tx = tid & 15, ty = tid >> 4;
    const bool masked = (*use_mask != 0);
    const int kmax = masked ? (m0 + 128) : NS;
    const int NT = kmax >> 5;

    __shared__ float Ps[2][32][128];
    __shared__ float Vs[2][32][64];
    __shared__ float sinv_s[128];

    float* Pb = P + (size_t)bh * NS * NS;
    const float* Vb = V + (size_t)bh * NS * HD;

    if (tid < 128) sinv_s[tid] = inv[(size_t)bh * NS + m0 + tid];

    const int pr0 = tid >> 3;
    const int pr1 = pr0 + 32;
    const int pr2 = pr0 + 64;
    const int pr3 = pr0 + 96;
    const int pkc = (tid & 7) << 2;
    const int vr0 = tid >> 4;
    const int vr1 = vr0 + 16;
    const int vc  = (tid & 15) << 2;

    float4 sp0, sp1, sp2, sp3, sv0, sv1;
    {
        sp0 = *(const float4*)(Pb + (size_t)(m0 + pr0) * NS + pkc);
        sp1 = *(const float4*)(Pb + (size_t)(m0 + pr1) * NS + pkc);
        sp2 = *(const float4*)(Pb + (size_t)(m0 + pr2) * NS + pkc);
        sp3 = *(const float4*)(Pb + (size_t)(m0 + pr3) * NS + pkc);
        sv0 = *(const float4*)(Vb + (size_t)vr0 * HD + vc);
        sv1 = *(const float4*)(Vb + (size_t)vr1 * HD + vc);
    }
    __syncthreads();
    {
        Ps[0][pkc+0][pr0] = sp0.x; Ps[0][pkc+1][pr0] = sp0.y;
        Ps[0][pkc+2][pr0] = sp0.z; Ps[0][pkc+3][pr0] = sp0.w;
        Ps[0][pkc+0][pr1] = sp1.x; Ps[0][pkc+1][pr1] = sp1.y;
        Ps[0][pkc+2][pr1] = sp1.z; Ps[0][pkc+3][pr1] = sp1.w;
        Ps[0][pkc+0][pr2] = sp2.x; Ps[0][pkc+1][pr2] = sp2.y;
        Ps[0][pkc+2][pr2] = sp2.z; Ps[0][pkc+3][pr2] = sp2.w;
        Ps[0][pkc+0][pr3] = sp3.x; Ps[0][pkc+1][pr3] = sp3.y;
        Ps[0][pkc+2][pr3] = sp3.z; Ps[0][pkc+3][pr3] = sp3.w;
        *(float4*)&Vs[0][vr0][vc] = sv0;
        *(float4*)&Vs[0][vr1][vc] = sv1;
        float s0 = sinv_s[pr0], s1 = sinv_s[pr1], s2 = sinv_s[pr2], s3 = sinv_s[pr3];
        float4 w;
        w.x = sp0.x*s0; w.y = sp0.y*s0; w.z = sp0.z*s0; w.w = sp0.w*s0;
        *(float4*)(Pb + (size_t)(m0 + pr0) * NS + pkc) = w;
        w.x = sp1.x*s1; w.y = sp1.y*s1; w.z = sp1.z*s1; w.w = sp1.w*s1;
        *(float4*)(Pb + (size_t)(m0 + pr1) * NS + pkc) = w;
        w.x = sp2.x*s2; w.y = sp2.y*s2; w.z = sp2.z*s2; w.w = sp2.w*s2;
        *(float4*)(Pb + (size_t)(m0 + pr2) * NS + pkc) = w;
        w.x = sp3.x*s3; w.y = sp3.y*s3; w.z = sp3.z*s3; w.w = sp3.w*s3;
        *(float4*)(Pb + (size_t)(m0 + pr3) * NS + pkc) = w;
    }

    float acc[8][4];
#pragma unroll
    for (int i = 0; i < 8; i++)
#pragma unroll
        for (int j = 0; j < 4; j++) acc[i][j] = 0.f;

    for (int t = 0; t < NT; t++) {
        __syncthreads();
        if (t + 1 < NT) {
            int kk0 = (t + 1) * 32;
            sp0 = *(const float4*)(Pb + (size_t)(m0 + pr0) * NS + kk0 + pkc);
            sp1 = *(const float4*)(Pb + (size_t)(m0 + pr1) * NS + kk0 + pkc);
            sp2 = *(const float4*)(Pb + (size_t)(m0 + pr2) * NS + kk0 + pkc);
            sp3 = *(const float4*)(Pb + (size_t)(m0 + pr3) * NS + kk0 + pkc);
            sv0 = *(const float4*)(Vb + (size_t)(kk0 + vr0) * HD + vc);
            sv1 = *(const float4*)(Vb + (size_t)(kk0 + vr1) * HD + vc);
        }
        const int cb = t & 1;
#pragma unroll
        for (int kk = 0; kk < 32; kk++) {
            float a[8], b[4];
            *(float4*)&a[0] = *(const float4*)&Ps[cb][kk][ty*8];
            *(float4*)&a[4] = *(const float4*)&Ps[cb][kk][ty*8 + 4];
            *(float4*)&b[0] = *(const float4*)&Vs[cb][kk][tx*4];
#pragma unroll
            for (int i = 0; i < 8; i++)
#pragma unroll
                for (int j = 0; j < 4; j++)
                    acc[i][j] = fmaf(a[i], b[j], acc[i][j]);
        }
        if (t + 1 < NT) {
            const int nb = (t + 1) & 1;
            const int kk0 = (t + 1) * 32;
            Ps[nb][pkc+0][pr0] = sp0.x; Ps[nb][pkc+1][pr0] = sp0.y;
            Ps[nb][pkc+2][pr0] = sp0.z; Ps[nb][pkc+3][pr0] = sp0.w;
            Ps[nb][pkc+0][pr1] = sp1.x; Ps[nb][pkc+1][pr1] = sp1.y;
            Ps[nb][pkc+2][pr1] = sp1.z; Ps[nb][pkc+3][pr1] = sp1.w;
            Ps[nb][pkc+0][pr2] = sp2.x; Ps[nb][pkc+1][pr2] = sp2.y;
            Ps[nb][pkc+2][pr2] = sp2.z; Ps[nb][pkc+3][pr2] = sp2.w;
            Ps[nb][pkc+0][pr3] = sp3.x; Ps[nb][pkc+1][pr3] = sp3.y;
            Ps[nb][pkc+2][pr3] = sp3.z; Ps[nb][pkc+3][pr3] = sp3.w;
            *(float4*)&Vs[nb][vr0][vc] = sv0;
            *(float4*)&Vs[nb][vr1][vc] = sv1;
            float s0 = sinv_s[pr0], s1 = sinv_s[pr1], s2 = sinv_s[pr2], s3 = sinv_s[pr3];
            float4 w;
            w.x = sp0.x*s0; w.y = sp0.y*s0; w.z = sp0.z*s0; w.w = sp0.w*s0;
            *(float4*)(Pb + (size_t)(m0 + pr0) * NS + kk0 + pkc) = w;
            w.x = sp1.x*s1; w.y = sp1.y*s1; w.z = sp1.z*s1; w.w = sp1.w*s1;
            *(float4*)(Pb + (size_t)(m0 + pr1) * NS + kk0 + pkc) = w;
            w.x = sp2.x*s2; w.y = sp2.y*s2; w.z = sp2.z*s2; w.w = sp2.w*s2;
            *(float4*)(Pb + (size_t)(m0 + pr2) * NS + kk0 + pkc) = w;
            w.x = sp3.x*s3; w.y = sp3.y*s3; w.z = sp3.z*s3; w.w = sp3.w*s3;
            *(float4*)(Pb + (size_t)(m0 + pr3) * NS + kk0 + pkc) = w;
        }
    }

#pragma unroll
    for (int i = 0; i < 8; i++) {
        int m = m0 + ty*8 + i;
        float si = sinv_s[ty*8 + i];
        float4 r;
        r.x = acc[i][0]*si; r.y = acc[i][1]*si;
        r.z = acc[i][2]*si; r.w = acc[i][3]*si;
        *(float4*)(O + ((size_t)bh * NS + m) * HD + tx*4) = r;
    }
}

// ---------------------------------------------------------------------------
extern "C" void kernel_launch(void* const* d_in, const int* in_sizes, int n_in,
                              void* d_out, int out_size)
{
    const float* q      = (const float*)d_in[0];
    const float* k      = (const float*)d_in[1];
    const float* v      = (const float*)d_in[2];
    const float* qkv_w  = (const float*)d_in[3];
    const float* proj_w = (const float*)d_in[4];
    const float* proj_b = (const float*)d_in[5];
    const int*   use_mask = (const int*)d_in[6];

    float* out      = (float*)d_out;
    float* x_out    = out;                       // (B, N, C)
    float* attn_out = out + (size_t)XSIZE;       // (B, H, N, N)

    float *qh, *kh, *vh, *ao, *part, *invs;
    cudaGetSymbolAddress((void**)&qh, g_qh);
    cudaGetSymbolAddress((void**)&kh, g_kh);
    cudaGetSymbolAddress((void**)&vh, g_vh);
    cudaGetSymbolAddress((void**)&ao, g_ao);
    cudaGetSymbolAddress((void**)&part, g_partial);
    cudaGetSymbolAddress((void**)&invs, g_inv);

    dim3 blk(256);

    // QKV projections on tensor cores (mma.sync tf32), head-transposed outputs
    mma_mm<0><<<dim3(CD/128, (BB*NS)/128, 3), blk>>>(q, k, v, qkv_w, qh, kh, vh, nullptr);

    // exp(scale * Q K^T) with mask -> attn_out (unnormalized) + partial sums
    score_exp_gemm<<<dim3(NS/128, NS/128, BB*HH), blk>>>(qh, kh, attn_out, part, use_mask);

    // Row inverse sums
    rowinv<<<(BB*HH*NS)/256, blk>>>(part, invs);

    // Normalize P (finalizing attn output) + P @ V
    av_gemm<<<dim3(NS/128, BB*HH), blk>>>(attn_out, vh, ao, invs, use_mask);

    // Output projection + bias on tensor cores
    mma_mm<1><<<dim3(CD/128, (BB*NS)/128, 1), blk>>>(ao, nullptr, nullptr, proj_w,
                                                     x_out, nullptr, nullptr, proj_b);
}

// round 12
// speedup vs baseline: 1.8708x; 1.1902x over previous
#include <cuda_runtime.h>
#include <cstdint>

#define BB 2
#define HH 16
#define NS 2048
#define HD 64
#define CD 1024
#define XSIZE (BB*NS*CD)
#define SCALE_F 0.125f
#define HSZ (BB*HH*NS*HD)

// Scratch (allocation-free rule: __device__ globals)
__device__ float g_qh[HSZ];              // (B,H,N,hd)
__device__ float g_kh[HSZ];
__device__ float g_vh[HSZ];
__device__ float g_ao[HSZ];              // attention output before proj
__device__ float g_partial[BB*HH*NS*16]; // per-(row, j-block) exp partial sums
__device__ float g_inv[BB*HH*NS];        // 1 / row sum

__device__ __forceinline__ uint32_t f2tf32(float x) {
    uint32_t y; asm("cvt.rna.tf32.f32 %0, %1;" : "=r"(y) : "f"(x)); return y;
}
__device__ __forceinline__ void mma_tf32(float& d0, float& d1, float& d2, float& d3,
                                         uint32_t a0, uint32_t a1, uint32_t a2, uint32_t a3,
                                         uint32_t b0, uint32_t b1) {
    asm volatile(
        "mma.sync.aligned.m16n8k8.row.col.f32.tf32.tf32.f32 "
        "{%0,%1,%2,%3}, {%4,%5,%6,%7}, {%8,%9}, {%0,%1,%2,%3};"
        : "+f"(d0), "+f"(d1), "+f"(d2), "+f"(d3)
        : "r"(a0), "r"(a1), "r"(a2), "r"(a3), "r"(b0), "r"(b1));
}

// ---------------------------------------------------------------------------
// TF32 mma.sync GEMM: Y[m,j] = sum_k A[m,k] * W[j,k].  256 thr = 8 warps
// (2 m x 4 n), warp tile 64x32, BM=BN=128, BK=16 (2 mma k-steps).
// MODE 0: qkv (A row-major, Y head-permuted).  MODE 1: proj (A head-gather,
// Y row-major + bias).
// ---------------------------------------------------------------------------
template<int MODE>
__global__ __launch_bounds__(256)
void mma_mm(const float* __restrict__ Aq, const float* __restrict__ Ak,
            const float* __restrict__ Av, const float* __restrict__ Wall,
            float* __restrict__ Yq, float* __restrict__ Yk,
            float* __restrict__ Yv, const float* __restrict__ bias)
{
    __shared__ uint32_t As[2][16][132];
    __shared__ uint32_t Bs[2][16][132];

    const int tid  = threadIdx.x;
    const int lane = tid & 31;
    const int warp = tid >> 5;
    const int wm = warp >> 2;            // 0..1
    const int wn = warp & 3;             // 0..3
    const int m0 = blockIdx.y * 128;
    const int n0 = blockIdx.x * 128;

    const float* A;
    const float* W;
    float* Y;
    if (MODE == 0) {
        const int z = blockIdx.z;
        A = (z == 0) ? Aq : (z == 1) ? Ak : Av;
        W = Wall + (size_t)z * CD * CD;
        Y = (z == 0) ? Yq : (z == 1) ? Yk : Yv;
    } else {
        A = Aq; W = Wall; Y = Yq;
    }

    const int r0  = tid >> 2;            // 0..63
    const int r1  = r0 + 64;
    const int kc0 = (tid & 3) << 2;

    int gb0 = 0, gn0 = 0, gb1 = 0, gn1 = 0;
    if (MODE == 1) {
        int mm0 = m0 + r0; gb0 = mm0 >> 11; gn0 = mm0 & (NS - 1);
        int mm1 = m0 + r1; gb1 = mm1 >> 11; gn1 = mm1 & (NS - 1);
    }

    float4 sa0, sa1, sw0, sw1;
    if (MODE == 0) {
        sa0 = *(const float4*)(A + (size_t)(m0 + r0) * CD + kc0);
        sa1 = *(const float4*)(A + (size_t)(m0 + r1) * CD + kc0);
    } else {
        sa0 = *(const float4*)(A + (((size_t)(gb0*HH + (kc0 >> 6)) * NS + gn0) * HD + (kc0 & 63)));
        sa1 = *(const float4*)(A + (((size_t)(gb1*HH + (kc0 >> 6)) * NS + gn1) * HD + (kc0 & 63)));
    }
    sw0 = *(const float4*)(W + (size_t)(n0 + r0) * CD + kc0);
    sw1 = *(const float4*)(W + (size_t)(n0 + r1) * CD + kc0);
    As[0][kc0+0][r0] = f2tf32(sa0.x); As[0][kc0+1][r0] = f2tf32(sa0.y);
    As[0][kc0+2][r0] = f2tf32(sa0.z); As[0][kc0+3][r0] = f2tf32(sa0.w);
    As[0][kc0+0][r1] = f2tf32(sa1.x); As[0][kc0+1][r1] = f2tf32(sa1.y);
    As[0][kc0+2][r1] = f2tf32(sa1.z); As[0][kc0+3][r1] = f2tf32(sa1.w);
    Bs[0][kc0+0][r0] = f2tf32(sw0.x); Bs[0][kc0+1][r0] = f2tf32(sw0.y);
    Bs[0][kc0+2][r0] = f2tf32(sw0.z); Bs[0][kc0+3][r0] = f2tf32(sw0.w);
    Bs[0][kc0+0][r1] = f2tf32(sw1.x); Bs[0][kc0+1][r1] = f2tf32(sw1.y);
    Bs[0][kc0+2][r1] = f2tf32(sw1.z); Bs[0][kc0+3][r1] = f2tf32(sw1.w);

    float acc[4][4][4];
#pragma unroll
    for (int i = 0; i < 4; i++)
#pragma unroll
        for (int j = 0; j < 4; j++)
#pragma unroll
            for (int c = 0; c < 4; c++) acc[i][j][c] = 0.f;

    const int lq = lane & 3;
    const int lr = lane >> 2;

    const int NT = CD / 16;
    for (int t = 0; t < NT; t++) {
        __syncthreads();
        if (t + 1 < NT) {
            int k = (t + 1) * 16 + kc0;
            if (MODE == 0) {
                sa0 = *(const float4*)(A + (size_t)(m0 + r0) * CD + k);
                sa1 = *(const float4*)(A + (size_t)(m0 + r1) * CD + k);
            } else {
                sa0 = *(const float4*)(A + (((size_t)(gb0*HH + (k >> 6)) * NS + gn0) * HD + (k & 63)));
                sa1 = *(const float4*)(A + (((size_t)(gb1*HH + (k >> 6)) * NS + gn1) * HD + (k & 63)));
            }
            sw0 = *(const float4*)(W + (size_t)(n0 + r0) * CD + k);
            sw1 = *(const float4*)(W + (size_t)(n0 + r1) * CD + k);
        }
        const int cb = t & 1;
#pragma unroll
        for (int ks = 0; ks < 2; ks++) {
            const int kb = ks * 8;
            uint32_t af[4][4], bf[4][2];
#pragma unroll
            for (int i = 0; i < 4; i++) {
                int m = wm * 64 + i * 16 + lr;
                af[i][0] = As[cb][kb + lq    ][m];
                af[i][1] = As[cb][kb + lq    ][m + 8];
                af[i][2] = As[cb][kb + lq + 4][m];
                af[i][3] = As[cb][kb + lq + 4][m + 8];
            }
#pragma unroll
            for (int j = 0; j < 4; j++) {
                int n = wn * 32 + j * 8 + lr;
                bf[j][0] = Bs[cb][kb + lq    ][n];
                bf[j][1] = Bs[cb][kb + lq + 4][n];
            }
#pragma unroll
            for (int i = 0; i < 4; i++)
#pragma unroll
                for (int j = 0; j < 4; j++)
                    mma_tf32(acc[i][j][0], acc[i][j][1], acc[i][j][2], acc[i][j][3],
                             af[i][0], af[i][1], af[i][2], af[i][3],
                             bf[j][0], bf[j][1]);
        }
        if (t + 1 < NT) {
            const int nb = (t + 1) & 1;
            As[nb][kc0+0][r0] = f2tf32(sa0.x); As[nb][kc0+1][r0] = f2tf32(sa0.y);
            As[nb][kc0+2][r0] = f2tf32(sa0.z); As[nb][kc0+3][r0] = f2tf32(sa0.w);
            As[nb][kc0+0][r1] = f2tf32(sa1.x); As[nb][kc0+1][r1] = f2tf32(sa1.y);
            As[nb][kc0+2][r1] = f2tf32(sa1.z); As[nb][kc0+3][r1] = f2tf32(sa1.w);
            Bs[nb][kc0+0][r0] = f2tf32(sw0.x); Bs[nb][kc0+1][r0] = f2tf32(sw0.y);
            Bs[nb][kc0+2][r0] = f2tf32(sw0.z); Bs[nb][kc0+3][r0] = f2tf32(sw0.w);
            Bs[nb][kc0+0][r1] = f2tf32(sw1.x); Bs[nb][kc0+1][r1] = f2tf32(sw1.y);
            Bs[nb][kc0+2][r1] = f2tf32(sw1.z); Bs[nb][kc0+3][r1] = f2tf32(sw1.w);
        }
    }

#pragma unroll
    for (int i = 0; i < 4; i++) {
#pragma unroll
        for (int j = 0; j < 4; j++) {
            int col = n0 + wn * 32 + j * 8 + 2 * lq;
            int mA = m0 + wm * 64 + i * 16 + lr;
            int mB = mA + 8;
            float2 v0, v1;
            v0.x = acc[i][j][0]; v0.y = acc[i][j][1];
            v1.x = acc[i][j][2]; v1.y = acc[i][j][3];
            if (MODE == 0) {
                int bA = mA >> 11, nA = mA & (NS - 1);
                int bB = mB >> 11, nB = mB & (NS - 1);
                int head = col >> 6, off = col & 63;
                *(float2*)(Y + (((size_t)(bA*HH + head) * NS + nA) * HD + off)) = v0;
                *(float2*)(Y + (((size_t)(bB*HH + head) * NS + nB) * HD + off)) = v1;
            } else {
                float bx = bias[col], by = bias[col + 1];
                v0.x += bx; v0.y += by;
                v1.x += bx; v1.y += by;
                *(float2*)(Y + (size_t)mA * CD + col) = v0;
                *(float2*)(Y + (size_t)mB * CD + col) = v1;
            }
        }
    }
}

// ---------------------------------------------------------------------------
// Scores -> exp(scale*dot) (masked -> 0), plus per-(row, j-block) partial sums.
// ---------------------------------------------------------------------------
__global__ __launch_bounds__(256)
void score_exp_gemm(const float* __restrict__ Q, const float* __restrict__ Kh,
                    float* __restrict__ P, float* __restrict__ partial,
                    const int* __restrict__ use_mask)
{
    const int bh = blockIdx.z;
    const int m0 = blockIdx.y * 128;
    const int j0 = blockIdx.x * 128;
    const int jblk = blockIdx.x;
    const int tid = threadIdx.x;
    const int tx = tid & 15, ty = tid >> 4;
    const bool masked = (*use_mask != 0);
    float* Pb = P + (size_t)bh * NS * NS;

    if (masked && j0 > m0 + 127) {
        const float4 zer = make_float4(0.f, 0.f, 0.f, 0.f);
#pragma unroll
        for (int i = 0; i < 8; i++) {
            int m = m0 + ty*8 + i;
#pragma unroll
            for (int j4 = 0; j4 < 2; j4++)
                *(float4*)(Pb + (size_t)m * NS + j0 + tx*8 + j4*4) = zer;
        }
        if (tid < 128)
            partial[((size_t)bh * NS + m0 + tid) * 16 + jblk] = 0.f;
        return;
    }

    __shared__ float Qs[32][128];
    __shared__ float Ks[32][128];
    const float* Qb = Q  + (size_t)bh * NS * HD;
    const float* Kb = Kh + (size_t)bh * NS * HD;

    float acc[8][8];
#pragma unroll
    for (int i = 0; i < 8; i++)
#pragma unroll
        for (int j = 0; j < 8; j++) acc[i][j] = 0.f;

    for (int k0 = 0; k0 < HD; k0 += 32) {
#pragma unroll
        for (int v = 0; v < 4; v++) {
            int lin = tid + v * 256;
            int row = lin >> 3;
            int kc  = (lin & 7) << 2;
            float4 qv = *(const float4*)(Qb + (size_t)(m0 + row) * HD + k0 + kc);
            Qs[kc+0][row] = qv.x; Qs[kc+1][row] = qv.y;
            Qs[kc+2][row] = qv.z; Qs[kc+3][row] = qv.w;
            float4 kv = *(const float4*)(Kb + (size_t)(j0 + row) * HD + k0 + kc);
            Ks[kc+0][row] = kv.x; Ks[kc+1][row] = kv.y;
            Ks[kc+2][row] = kv.z; Ks[kc+3][row] = kv.w;
        }
        __syncthreads();
#pragma unroll
        for (int kk = 0; kk < 32; kk++) {
            float a[8], b[8];
            *(float4*)&a[0] = *(const float4*)&Qs[kk][ty*8];
            *(float4*)&a[4] = *(const float4*)&Qs[kk][ty*8 + 4];
            *(float4*)&b[0] = *(const float4*)&Ks[kk][tx*8];
            *(float4*)&b[4] = *(const float4*)&Ks[kk][tx*8 + 4];
#pragma unroll
            for (int i = 0; i < 8; i++)
#pragma unroll
                for (int j = 0; j < 8; j++)
                    acc[i][j] = fmaf(a[i], b[j], acc[i][j]);
        }
        __syncthreads();
    }

    __syncthreads();
    float* Srow = &Qs[0][0];          // 128 x 16, stride 17
#pragma unroll
    for (int i = 0; i < 8; i++) {
        int m = m0 + ty*8 + i;
        float rs = 0.f;
#pragma unroll
        for (int j4 = 0; j4 < 2; j4++) {
            int j = j0 + tx*8 + j4*4;
            float4 r;
            r.x = (masked && (j+0) > m) ? 0.f : __expf(acc[i][j4*4+0] * SCALE_F);
            r.y = (masked && (j+1) > m) ? 0.f : __expf(acc[i][j4*4+1] * SCALE_F);
            r.z = (masked && (j+2) > m) ? 0.f : __expf(acc[i][j4*4+2] * SCALE_F);
            r.w = (masked && (j+3) > m) ? 0.f : __expf(acc[i][j4*4+3] * SCALE_F);
            rs += r.x + r.y + r.z + r.w;
            *(float4*)(Pb + (size_t)m * NS + j) = r;
        }
        Srow[(ty*8 + i) * 17 + tx] = rs;
    }
    __syncthreads();
    if (tid < 128) {
        float s = 0.f;
#pragma unroll
        for (int t = 0; t < 16; t++) s += Srow[tid * 17 + t];
        partial[((size_t)bh * NS + m0 + tid) * 16 + jblk] = s;
    }
}

// ---------------------------------------------------------------------------
__global__ __launch_bounds__(256)
void rowinv(const float* __restrict__ partial, float* __restrict__ inv)
{
    int r = blockIdx.x * 256 + threadIdx.x;
    const float4* p = (const float4*)(partial + (size_t)r * 16);
    float4 a = p[0], b = p[1], c = p[2], d = p[3];
    float s = (a.x + a.y + a.z + a.w) + (b.x + b.y + b.z + b.w)
            + (c.x + c.y + c.z + c.w) + (d.x + d.y + d.z + d.w);
    inv[r] = 1.f / s;
}

// ---------------------------------------------------------------------------
// O = softmax(P) @ V on tensor cores (tf32 mma.sync). 8 warps as 4m x 2n,
// warp tile 32x32, BM=128, BN=64, BK=32 (4 k-steps). GEMM runs on tf32-rounded
// raw exp-P (smem only); the fp32 normalized P write-back uses the exact
// loaded values. Vs staged [k][n] (fixed from R11's transposed OOB staging).
// ---------------------------------------------------------------------------
__global__ __launch_bounds__(256)
void av_mma(float* __restrict__ P, const float* __restrict__ V,
            float* __restrict__ O, const float* __restrict__ inv,
            const int* __restrict__ use_mask)
{
    const int bh = blockIdx.y;
    const int m0 = ((int)gridDim.x - 1 - (int)blockIdx.x) * 128;
    const int tid = threadIdx.x;
    const int lane = tid & 31;
    const int warp = tid >> 5;
    const int wm = warp >> 1;            // 0..3
    const int wn = warp & 1;             // 0..1
    const bool masked = (*use_mask != 0);
    const int kmax = masked ? (m0 + 128) : NS;
    const int NT = kmax >> 5;

    __shared__ uint32_t Ps[2][32][132];  // [buf][k][m]
    __shared__ uint32_t Vs[2][32][68];   // [buf][k][n]
    __shared__ float sinv_s[128];

    float* Pb = P + (size_t)bh * NS * NS;
    const float* Vb = V + (size_t)bh * NS * HD;

    if (tid < 128) sinv_s[tid] = inv[(size_t)bh * NS + m0 + tid];

    const int pr0 = tid >> 3;            // 0..31
    const int pr1 = pr0 + 32;
    const int pr2 = pr0 + 64;
    const int pr3 = pr0 + 96;
    const int pkc = (tid & 7) << 2;
    const int vr0 = tid >> 4;            // 0..15  (k row)
    const int vr1 = vr0 + 16;
    const int vc  = (tid & 15) << 2;     // 0..60  (n col)

    float4 sp0, sp1, sp2, sp3, sv0, sv1;
    // prologue: tile 0 loads
    sp0 = *(const float4*)(Pb + (size_t)(m0 + pr0) * NS + pkc);
    sp1 = *(const float4*)(Pb + (size_t)(m0 + pr1) * NS + pkc);
    sp2 = *(const float4*)(Pb + (size_t)(m0 + pr2) * NS + pkc);
    sp3 = *(const float4*)(Pb + (size_t)(m0 + pr3) * NS + pkc);
    sv0 = *(const float4*)(Vb + (size_t)vr0 * HD + vc);
    sv1 = *(const float4*)(Vb + (size_t)vr1 * HD + vc);
    __syncthreads();                     // sinv_s visible
    {
        Ps[0][pkc+0][pr0] = f2tf32(sp0.x); Ps[0][pkc+1][pr0] = f2tf32(sp0.y);
        Ps[0][pkc+2][pr0] = f2tf32(sp0.z); Ps[0][pkc+3][pr0] = f2tf32(sp0.w);
        Ps[0][pkc+0][pr1] = f2tf32(sp1.x); Ps[0][pkc+1][pr1] = f2tf32(sp1.y);
        Ps[0][pkc+2][pr1] = f2tf32(sp1.z); Ps[0][pkc+3][pr1] = f2tf32(sp1.w);
        Ps[0][pkc+0][pr2] = f2tf32(sp2.x); Ps[0][pkc+1][pr2] = f2tf32(sp2.y);
        Ps[0][pkc+2][pr2] = f2tf32(sp2.z); Ps[0][pkc+3][pr2] = f2tf32(sp2.w);
        Ps[0][pkc+0][pr3] = f2tf32(sp3.x); Ps[0][pkc+1][pr3] = f2tf32(sp3.y);
        Ps[0][pkc+2][pr3] = f2tf32(sp3.z); Ps[0][pkc+3][pr3] = f2tf32(sp3.w);
        Vs[0][vr0][vc+0] = f2tf32(sv0.x); Vs[0][vr0][vc+1] = f2tf32(sv0.y);
        Vs[0][vr0][vc+2] = f2tf32(sv0.z); Vs[0][vr0][vc+3] = f2tf32(sv0.w);
        Vs[0][vr1][vc+0] = f2tf32(sv1.x); Vs[0][vr1][vc+1] = f2tf32(sv1.y);
        Vs[0][vr1][vc+2] = f2tf32(sv1.z); Vs[0][vr1][vc+3] = f2tf32(sv1.w);
        float s0 = sinv_s[pr0], s1 = sinv_s[pr1], s2 = sinv_s[pr2], s3 = sinv_s[pr3];
        float4 w;
        w.x = sp0.x*s0; w.y = sp0.y*s0; w.z = sp0.z*s0; w.w = sp0.w*s0;
        *(float4*)(Pb + (size_t)(m0 + pr0) * NS + pkc) = w;
        w.x = sp1.x*s1; w.y = sp1.y*s1; w.z = sp1.z*s1; w.w = sp1.w*s1;
        *(float4*)(Pb + (size_t)(m0 + pr1) * NS + pkc) = w;
        w.x = sp2.x*s2; w.y = sp2.y*s2; w.z = sp2.z*s2; w.w = sp2.w*s2;
        *(float4*)(Pb + (size_t)(m0 + pr2) * NS + pkc) = w;
        w.x = sp3.x*s3; w.y = sp3.y*s3; w.z = sp3.z*s3; w.w = sp3.w*s3;
        *(float4*)(Pb + (size_t)(m0 + pr3) * NS + pkc) = w;
    }

    float acc[2][4][4];
#pragma unroll
    for (int i = 0; i < 2; i++)
#pragma unroll
        for (int j = 0; j < 4; j++)
#pragma unroll
            for (int c = 0; c < 4; c++) acc[i][j][c] = 0.f;

    const int lq = lane & 3;
    const int lr = lane >> 2;

    for (int t = 0; t < NT; t++) {
        __syncthreads();
        if (t + 1 < NT) {
            int kk0 = (t + 1) * 32;
            sp0 = *(const float4*)(Pb + (size_t)(m0 + pr0) * NS + kk0 + pkc);
            sp1 = *(const float4*)(Pb + (size_t)(m0 + pr1) * NS + kk0 + pkc);
            sp2 = *(const float4*)(Pb + (size_t)(m0 + pr2) * NS + kk0 + pkc);
            sp3 = *(const float4*)(Pb + (size_t)(m0 + pr3) * NS + kk0 + pkc);
            sv0 = *(const float4*)(Vb + (size_t)(kk0 + vr0) * HD + vc);
            sv1 = *(const float4*)(Vb + (size_t)(kk0 + vr1) * HD + vc);
        }
        const int cb = t & 1;
#pragma unroll
        for (int ks = 0; ks < 4; ks++) {
            const int kb = ks * 8;
            uint32_t af[2][4], bf[4][2];
#pragma unroll
            for (int i = 0; i < 2; i++) {
                int m = wm * 32 + i * 16 + lr;
                af[i][0] = Ps[cb][kb + lq    ][m];
                af[i][1] = Ps[cb][kb + lq    ][m + 8];
                af[i][2] = Ps[cb][kb + lq + 4][m];
                af[i][3] = Ps[cb][kb + lq + 4][m + 8];
            }
#pragma unroll
            for (int j = 0; j < 4; j++) {
                int n = wn * 32 + j * 8 + lr;
                bf[j][0] = Vs[cb][kb + lq    ][n];
                bf[j][1] = Vs[cb][kb + lq + 4][n];
            }
#pragma unroll
            for (int i = 0; i < 2; i++)
#pragma unroll
                for (int j = 0; j < 4; j++)
                    mma_tf32(acc[i][j][0], acc[i][j][1], acc[i][j][2], acc[i][j][3],
                             af[i][0], af[i][1], af[i][2], af[i][3],
                             bf[j][0], bf[j][1]);
        }
        if (t + 1 < NT) {
            const int nb = (t + 1) & 1;
            const int kk0 = (t + 1) * 32;
            Ps[nb][pkc+0][pr0] = f2tf32(sp0.x); Ps[nb][pkc+1][pr0] = f2tf32(sp0.y);
            Ps[nb][pkc+2][pr0] = f2tf32(sp0.z); Ps[nb][pkc+3][pr0] = f2tf32(sp0.w);
            Ps[nb][pkc+0][pr1] = f2tf32(sp1.x); Ps[nb][pkc+1][pr1] = f2tf32(sp1.y);
            Ps[nb][pkc+2][pr1] = f2tf32(sp1.z); Ps[nb][pkc+3][pr1] = f2tf32(sp1.w);
            Ps[nb][pkc+0][pr2] = f2tf32(sp2.x); Ps[nb][pkc+1][pr2] = f2tf32(sp2.y);
            Ps[nb][pkc+2][pr2] = f2tf32(sp2.z); Ps[nb][pkc+3][pr2] = f2tf32(sp2.w);
            Ps[nb][pkc+0][pr3] = f2tf32(sp3.x); Ps[nb][pkc+1][pr3] = f2tf32(sp3.y);
            Ps[nb][pkc+2][pr3] = f2tf32(sp3.z); Ps[nb][pkc+3][pr3] = f2tf32(sp3.w);
            Vs[nb][vr0][vc+0] = f2tf32(sv0.x); Vs[nb][vr0][vc+1] = f2tf32(sv0.y);
            Vs[nb][vr0][vc+2] = f2tf32(sv0.z); Vs[nb][vr0][vc+3] = f2tf32(sv0.w);
            Vs[nb][vr1][vc+0] = f2tf32(sv1.x); Vs[nb][vr1][vc+1] = f2tf32(sv1.y);
            Vs[nb][vr1][vc+2] = f2tf32(sv1.z); Vs[nb][vr1][vc+3] = f2tf32(sv1.w);
            float s0 = sinv_s[pr0], s1 = sinv_s[pr1], s2 = sinv_s[pr2], s3 = sinv_s[pr3];
            float4 w;
            w.x = sp0.x*s0; w.y = sp0.y*s0; w.z = sp0.z*s0; w.w = sp0.w*s0;
            *(float4*)(Pb + (size_t)(m0 + pr0) * NS + kk0 + pkc) = w;
            w.x = sp1.x*s1; w.y = sp1.y*s1; w.z = sp1.z*s1; w.w = sp1.w*s1;
            *(float4*)(Pb + (size_t)(m0 + pr1) * NS + kk0 + pkc) = w;
            w.x = sp2.x*s2; w.y = sp2.y*s2; w.z = sp2.z*s2; w.w = sp2.w*s2;
            *(float4*)(Pb + (size_t)(m0 + pr2) * NS + kk0 + pkc) = w;
            w.x = sp3.x*s3; w.y = sp3.y*s3; w.z = sp3.z*s3; w.w = sp3.w*s3;
            *(float4*)(Pb + (size_t)(m0 + pr3) * NS + kk0 + pkc) = w;
        }
    }

    // Epilogue: scale by sinv, store
#pragma unroll
    for (int i = 0; i < 2; i++) {
#pragma unroll
        for (int j = 0; j < 4; j++) {
            int col = wn * 32 + j * 8 + 2 * lq;
            int lmA = wm * 32 + i * 16 + lr;
            int lmB = lmA + 8;
            float sA = sinv_s[lmA], sB = sinv_s[lmB];
            float2 v0, v1;
            v0.x = acc[i][j][0] * sA; v0.y = acc[i][j][1] * sA;
            v1.x = acc[i][j][2] * sB; v1.y = acc[i][j][3] * sB;
            *(float2*)(O + ((size_t)bh * NS + m0 + lmA) * HD + col) = v0;
            *(float2*)(O + ((size_t)bh * NS + m0 + lmB) * HD + col) = v1;
        }
    }
}

// ---------------------------------------------------------------------------
extern "C" void kernel_launch(void* const* d_in, const int* in_sizes, int n_in,
                              void* d_out, int out_size)
{
    const float* q      = (const float*)d_in[0];
    const float* k      = (const float*)d_in[1];
    const float* v      = (const float*)d_in[2];
    const float* qkv_w  = (const float*)d_in[3];
    const float* proj_w = (const float*)d_in[4];
    const float* proj_b = (const float*)d_in[5];
    const int*   use_mask = (const int*)d_in[6];

    float* out      = (float*)d_out;
    float* x_out    = out;                       // (B, N, C)
    float* attn_out = out + (size_t)XSIZE;       // (B, H, N, N)

    float *qh, *kh, *vh, *ao, *part, *invs;
    cudaGetSymbolAddress((void**)&qh, g_qh);
    cudaGetSymbolAddress((void**)&kh, g_kh);
    cudaGetSymbolAddress((void**)&vh, g_vh);
    cudaGetSymbolAddress((void**)&ao, g_ao);
    cudaGetSymbolAddress((void**)&part, g_partial);
    cudaGetSymbolAddress((void**)&invs, g_inv);

    dim3 blk(256);

    // QKV projections on tensor cores (mma.sync tf32), head-transposed outputs
    mma_mm<0><<<dim3(CD/128, (BB*NS)/128, 3), blk>>>(q, k, v, qkv_w, qh, kh, vh, nullptr);

    // exp(scale * Q K^T) with mask -> attn_out (unnormalized) + partial sums
    score_exp_gemm<<<dim3(NS/128, NS/128, BB*HH), blk>>>(qh, kh, attn_out, part, use_mask);

    // Row inverse sums
    rowinv<<<(BB*HH*NS)/256, blk>>>(part, invs);

    // Normalize P (finalizing attn output) + P @ V on tensor cores
    av_mma<<<dim3(NS/128, BB*HH), blk>>>(attn_out, vh, ao, invs, use_mask);

    // Output projection + bias on tensor cores
    mma_mm<1><<<dim3(CD/128, (BB*NS)/128, 1), blk>>>(ao, nullptr, nullptr, proj_w,
                                                     x_out, nullptr, nullptr, proj_b);
}

// round 13
// speedup vs baseline: 1.8826x; 1.0063x over previous
#include <cuda_runtime.h>
#include <cstdint>

#define BB 2
#define HH 16
#define NS 2048
#define HD 64
#define CD 1024
#define XSIZE (BB*NS*CD)
#define SCALE_F 0.125f
#define HSZ (BB*HH*NS*HD)

// Scratch (allocation-free rule: __device__ globals)
__device__ float g_qh[HSZ];              // (B,H,N,hd)
__device__ float g_kh[HSZ];
__device__ float g_vh[HSZ];
__device__ float g_ao[HSZ];              // attention output before proj
__device__ float g_partial[BB*HH*NS*16]; // per-(row, j-block) exp partial sums
__device__ float g_inv[BB*HH*NS];        // 1 / row sum

__device__ __forceinline__ uint32_t f2tf32(float x) {
    uint32_t y; asm("cvt.rna.tf32.f32 %0, %1;" : "=r"(y) : "f"(x)); return y;
}
__device__ __forceinline__ void tf32_split(float x, uint32_t& hi, uint32_t& lo) {
    hi = f2tf32(x);
    lo = f2tf32(x - __uint_as_float(hi));
}
__device__ __forceinline__ void mma_tf32(float& d0, float& d1, float& d2, float& d3,
                                         uint32_t a0, uint32_t a1, uint32_t a2, uint32_t a3,
                                         uint32_t b0, uint32_t b1) {
    asm volatile(
        "mma.sync.aligned.m16n8k8.row.col.f32.tf32.tf32.f32 "
        "{%0,%1,%2,%3}, {%4,%5,%6,%7}, {%8,%9}, {%0,%1,%2,%3};"
        : "+f"(d0), "+f"(d1), "+f"(d2), "+f"(d3)
        : "r"(a0), "r"(a1), "r"(a2), "r"(a3), "r"(b0), "r"(b1));
}

// ---------------------------------------------------------------------------
// TF32 mma.sync GEMM: Y[m,j] = sum_k A[m,k] * W[j,k].  256 thr = 8 warps
// (2 m x 4 n), warp tile 64x32, BM=BN=128, BK=16 (2 mma k-steps).
// MODE 0: qkv (A row-major, Y head-permuted).  MODE 1: proj (A head-gather,
// Y row-major + bias).
// ---------------------------------------------------------------------------
template<int MODE>
__global__ __launch_bounds__(256)
void mma_mm(const float* __restrict__ Aq, const float* __restrict__ Ak,
            const float* __restrict__ Av, const float* __restrict__ Wall,
            float* __restrict__ Yq, float* __restrict__ Yk,
            float* __restrict__ Yv, const float* __restrict__ bias)
{
    __shared__ uint32_t As[2][16][132];
    __shared__ uint32_t Bs[2][16][132];

    const int tid  = threadIdx.x;
    const int lane = tid & 31;
    const int warp = tid >> 5;
    const int wm = warp >> 2;            // 0..1
    const int wn = warp & 3;             // 0..3
    const int m0 = blockIdx.y * 128;
    const int n0 = blockIdx.x * 128;

    const float* A;
    const float* W;
    float* Y;
    if (MODE == 0) {
        const int z = blockIdx.z;
        A = (z == 0) ? Aq : (z == 1) ? Ak : Av;
        W = Wall + (size_t)z * CD * CD;
        Y = (z == 0) ? Yq : (z == 1) ? Yk : Yv;
    } else {
        A = Aq; W = Wall; Y = Yq;
    }

    const int r0  = tid >> 2;            // 0..63
    const int r1  = r0 + 64;
    const int kc0 = (tid & 3) << 2;

    int gb0 = 0, gn0 = 0, gb1 = 0, gn1 = 0;
    if (MODE == 1) {
        int mm0 = m0 + r0; gb0 = mm0 >> 11; gn0 = mm0 & (NS - 1);
        int mm1 = m0 + r1; gb1 = mm1 >> 11; gn1 = mm1 & (NS - 1);
    }

    float4 sa0, sa1, sw0, sw1;
    if (MODE == 0) {
        sa0 = *(const float4*)(A + (size_t)(m0 + r0) * CD + kc0);
        sa1 = *(const float4*)(A + (size_t)(m0 + r1) * CD + kc0);
    } else {
        sa0 = *(const float4*)(A + (((size_t)(gb0*HH + (kc0 >> 6)) * NS + gn0) * HD + (kc0 & 63)));
        sa1 = *(const float4*)(A + (((size_t)(gb1*HH + (kc0 >> 6)) * NS + gn1) * HD + (kc0 & 63)));
    }
    sw0 = *(const float4*)(W + (size_t)(n0 + r0) * CD + kc0);
    sw1 = *(const float4*)(W + (size_t)(n0 + r1) * CD + kc0);
    As[0][kc0+0][r0] = f2tf32(sa0.x); As[0][kc0+1][r0] = f2tf32(sa0.y);
    As[0][kc0+2][r0] = f2tf32(sa0.z); As[0][kc0+3][r0] = f2tf32(sa0.w);
    As[0][kc0+0][r1] = f2tf32(sa1.x); As[0][kc0+1][r1] = f2tf32(sa1.y);
    As[0][kc0+2][r1] = f2tf32(sa1.z); As[0][kc0+3][r1] = f2tf32(sa1.w);
    Bs[0][kc0+0][r0] = f2tf32(sw0.x); Bs[0][kc0+1][r0] = f2tf32(sw0.y);
    Bs[0][kc0+2][r0] = f2tf32(sw0.z); Bs[0][kc0+3][r0] = f2tf32(sw0.w);
    Bs[0][kc0+0][r1] = f2tf32(sw1.x); Bs[0][kc0+1][r1] = f2tf32(sw1.y);
    Bs[0][kc0+2][r1] = f2tf32(sw1.z); Bs[0][kc0+3][r1] = f2tf32(sw1.w);

    float acc[4][4][4];
#pragma unroll
    for (int i = 0; i < 4; i++)
#pragma unroll
        for (int j = 0; j < 4; j++)
#pragma unroll
            for (int c = 0; c < 4; c++) acc[i][j][c] = 0.f;

    const int lq = lane & 3;
    const int lr = lane >> 2;

    const int NT = CD / 16;
    for (int t = 0; t < NT; t++) {
        __syncthreads();
        if (t + 1 < NT) {
            int k = (t + 1) * 16 + kc0;
            if (MODE == 0) {
                sa0 = *(const float4*)(A + (size_t)(m0 + r0) * CD + k);
                sa1 = *(const float4*)(A + (size_t)(m0 + r1) * CD + k);
            } else {
                sa0 = *(const float4*)(A + (((size_t)(gb0*HH + (k >> 6)) * NS + gn0) * HD + (k & 63)));
                sa1 = *(const float4*)(A + (((size_t)(gb1*HH + (k >> 6)) * NS + gn1) * HD + (k & 63)));
            }
            sw0 = *(const float4*)(W + (size_t)(n0 + r0) * CD + k);
            sw1 = *(const float4*)(W + (size_t)(n0 + r1) * CD + k);
        }
        const int cb = t & 1;
#pragma unroll
        for (int ks = 0; ks < 2; ks++) {
            const int kb = ks * 8;
            uint32_t af[4][4], bf[4][2];
#pragma unroll
            for (int i = 0; i < 4; i++) {
                int m = wm * 64 + i * 16 + lr;
                af[i][0] = As[cb][kb + lq    ][m];
                af[i][1] = As[cb][kb + lq    ][m + 8];
                af[i][2] = As[cb][kb + lq + 4][m];
                af[i][3] = As[cb][kb + lq + 4][m + 8];
            }
#pragma unroll
            for (int j = 0; j < 4; j++) {
                int n = wn * 32 + j * 8 + lr;
                bf[j][0] = Bs[cb][kb + lq    ][n];
                bf[j][1] = Bs[cb][kb + lq + 4][n];
            }
#pragma unroll
            for (int i = 0; i < 4; i++)
#pragma unroll
                for (int j = 0; j < 4; j++)
                    mma_tf32(acc[i][j][0], acc[i][j][1], acc[i][j][2], acc[i][j][3],
                             af[i][0], af[i][1], af[i][2], af[i][3],
                             bf[j][0], bf[j][1]);
        }
        if (t + 1 < NT) {
            const int nb = (t + 1) & 1;
            As[nb][kc0+0][r0] = f2tf32(sa0.x); As[nb][kc0+1][r0] = f2tf32(sa0.y);
            As[nb][kc0+2][r0] = f2tf32(sa0.z); As[nb][kc0+3][r0] = f2tf32(sa0.w);
            As[nb][kc0+0][r1] = f2tf32(sa1.x); As[nb][kc0+1][r1] = f2tf32(sa1.y);
            As[nb][kc0+2][r1] = f2tf32(sa1.z); As[nb][kc0+3][r1] = f2tf32(sa1.w);
            Bs[nb][kc0+0][r0] = f2tf32(sw0.x); Bs[nb][kc0+1][r0] = f2tf32(sw0.y);
            Bs[nb][kc0+2][r0] = f2tf32(sw0.z); Bs[nb][kc0+3][r0] = f2tf32(sw0.w);
            Bs[nb][kc0+0][r1] = f2tf32(sw1.x); Bs[nb][kc0+1][r1] = f2tf32(sw1.y);
            Bs[nb][kc0+2][r1] = f2tf32(sw1.z); Bs[nb][kc0+3][r1] = f2tf32(sw1.w);
        }
    }

#pragma unroll
    for (int i = 0; i < 4; i++) {
#pragma unroll
        for (int j = 0; j < 4; j++) {
            int col = n0 + wn * 32 + j * 8 + 2 * lq;
            int mA = m0 + wm * 64 + i * 16 + lr;
            int mB = mA + 8;
            float2 v0, v1;
            v0.x = acc[i][j][0]; v0.y = acc[i][j][1];
            v1.x = acc[i][j][2]; v1.y = acc[i][j][3];
            if (MODE == 0) {
                int bA = mA >> 11, nA = mA & (NS - 1);
                int bB = mB >> 11, nB = mB & (NS - 1);
                int head = col >> 6, off = col & 63;
                *(float2*)(Y + (((size_t)(bA*HH + head) * NS + nA) * HD + off)) = v0;
                *(float2*)(Y + (((size_t)(bB*HH + head) * NS + nB) * HD + off)) = v1;
            } else {
                float bx = bias[col], by = bias[col + 1];
                v0.x += bx; v0.y += by;
                v1.x += bx; v1.y += by;
                *(float2*)(Y + (size_t)mA * CD + col) = v0;
                *(float2*)(Y + (size_t)mB * CD + col) = v1;
            }
        }
    }
}

// ---------------------------------------------------------------------------
// Scores on tensor cores with 3xTF32 compensation (fp32-accurate):
// P = exp(scale * Qh Kh^T) with causal mask -> 0, plus per-(row,jblk) partial
// sums. 8 warps as 2m x 4n, warp tile 64x32, BK=16 x 4 tiles.
// acc += Qhi*Khi + Qhi*Klo + Qlo*Khi  (lo*lo term negligible).
// ---------------------------------------------------------------------------
__global__ __launch_bounds__(256)
void score_mma(const float* __restrict__ Q, const float* __restrict__ Kh,
               float* __restrict__ P, float* __restrict__ partial,
               const int* __restrict__ use_mask)
{
    const int bh = blockIdx.z;
    const int m0 = blockIdx.y * 128;
    const int j0 = blockIdx.x * 128;
    const int jblk = blockIdx.x;
    const int tid = threadIdx.x;
    const int lane = tid & 31;
    const int warp = tid >> 5;
    const int wm = warp >> 2;            // 0..1
    const int wn = warp & 3;             // 0..3
    const bool masked = (*use_mask != 0);
    float* Pb = P + (size_t)bh * NS * NS;

    if (masked && j0 > m0 + 127) {
        // fully-masked tile: zero writes + zero partials
        const int zr = tid >> 1;                 // 0..127
        const int zc = (tid & 1) * 64;
        float4 zer = make_float4(0.f, 0.f, 0.f, 0.f);
#pragma unroll
        for (int c = 0; c < 16; c++)
            *(float4*)(Pb + (size_t)(m0 + zr) * NS + j0 + zc + c * 4) = zer;
        if (tid < 128)
            partial[((size_t)bh * NS + m0 + tid) * 16 + jblk] = 0.f;
        return;
    }

    __shared__ uint32_t Qhi[16][132], Qlo[16][132];
    __shared__ uint32_t KhiS[16][132], KloS[16][132];
    __shared__ float Srow[128][17];

    const float* Qb = Q  + (size_t)bh * NS * HD;
    const float* Kb = Kh + (size_t)bh * NS * HD;

    const int r0  = tid >> 2;            // 0..63
    const int r1  = r0 + 64;
    const int kc0 = (tid & 3) << 2;

    float acc[4][4][4];
#pragma unroll
    for (int i = 0; i < 4; i++)
#pragma unroll
        for (int j = 0; j < 4; j++)
#pragma unroll
            for (int c = 0; c < 4; c++) acc[i][j][c] = 0.f;

    const int lq = lane & 3;
    const int lr = lane >> 2;

#pragma unroll
    for (int t = 0; t < 4; t++) {
        const int k0 = t * 16;
        float4 q0 = *(const float4*)(Qb + (size_t)(m0 + r0) * HD + k0 + kc0);
        float4 q1 = *(const float4*)(Qb + (size_t)(m0 + r1) * HD + k0 + kc0);
        float4 kv0 = *(const float4*)(Kb + (size_t)(j0 + r0) * HD + k0 + kc0);
        float4 kv1 = *(const float4*)(Kb + (size_t)(j0 + r1) * HD + k0 + kc0);
        __syncthreads();                 // prior tile's fragment reads done
        {
            uint32_t h, l;
            tf32_split(q0.x, h, l); Qhi[kc0+0][r0] = h; Qlo[kc0+0][r0] = l;
            tf32_split(q0.y, h, l); Qhi[kc0+1][r0] = h; Qlo[kc0+1][r0] = l;
            tf32_split(q0.z, h, l); Qhi[kc0+2][r0] = h; Qlo[kc0+2][r0] = l;
            tf32_split(q0.w, h, l); Qhi[kc0+3][r0] = h; Qlo[kc0+3][r0] = l;
            tf32_split(q1.x, h, l); Qhi[kc0+0][r1] = h; Qlo[kc0+0][r1] = l;
            tf32_split(q1.y, h, l); Qhi[kc0+1][r1] = h; Qlo[kc0+1][r1] = l;
            tf32_split(q1.z, h, l); Qhi[kc0+2][r1] = h; Qlo[kc0+2][r1] = l;
            tf32_split(q1.w, h, l); Qhi[kc0+3][r1] = h; Qlo[kc0+3][r1] = l;
            tf32_split(kv0.x, h, l); KhiS[kc0+0][r0] = h; KloS[kc0+0][r0] = l;
            tf32_split(kv0.y, h, l); KhiS[kc0+1][r0] = h; KloS[kc0+1][r0] = l;
            tf32_split(kv0.z, h, l); KhiS[kc0+2][r0] = h; KloS[kc0+2][r0] = l;
            tf32_split(kv0.w, h, l); KhiS[kc0+3][r0] = h; KloS[kc0+3][r0] = l;
            tf32_split(kv1.x, h, l); KhiS[kc0+0][r1] = h; KloS[kc0+0][r1] = l;
            tf32_split(kv1.y, h, l); KhiS[kc0+1][r1] = h; KloS[kc0+1][r1] = l;
            tf32_split(kv1.z, h, l); KhiS[kc0+2][r1] = h; KloS[kc0+2][r1] = l;
            tf32_split(kv1.w, h, l); KhiS[kc0+3][r1] = h; KloS[kc0+3][r1] = l;
        }
        __syncthreads();
#pragma unroll
        for (int ks = 0; ks < 2; ks++) {
            const int kb = ks * 8;
            uint32_t ah[4][4], al[4][4], bh2[4][2], bl2[4][2];
#pragma unroll
            for (int i = 0; i < 4; i++) {
                int m = wm * 64 + i * 16 + lr;
                ah[i][0] = Qhi[kb + lq    ][m];
                ah[i][1] = Qhi[kb + lq    ][m + 8];
                ah[i][2] = Qhi[kb + lq + 4][m];
                ah[i][3] = Qhi[kb + lq + 4][m + 8];
                al[i][0] = Qlo[kb + lq    ][m];
                al[i][1] = Qlo[kb + lq    ][m + 8];
                al[i][2] = Qlo[kb + lq + 4][m];
                al[i][3] = Qlo[kb + lq + 4][m + 8];
            }
#pragma unroll
            for (int j = 0; j < 4; j++) {
                int n = wn * 32 + j * 8 + lr;
                bh2[j][0] = KhiS[kb + lq    ][n];
                bh2[j][1] = KhiS[kb + lq + 4][n];
                bl2[j][0] = KloS[kb + lq    ][n];
                bl2[j][1] = KloS[kb + lq + 4][n];
            }
#pragma unroll
            for (int i = 0; i < 4; i++)
#pragma unroll
                for (int j = 0; j < 4; j++) {
                    mma_tf32(acc[i][j][0], acc[i][j][1], acc[i][j][2], acc[i][j][3],
                             ah[i][0], ah[i][1], ah[i][2], ah[i][3],
                             bh2[j][0], bh2[j][1]);
                    mma_tf32(acc[i][j][0], acc[i][j][1], acc[i][j][2], acc[i][j][3],
                             ah[i][0], ah[i][1], ah[i][2], ah[i][3],
                             bl2[j][0], bl2[j][1]);
                    mma_tf32(acc[i][j][0], acc[i][j][1], acc[i][j][2], acc[i][j][3],
                             al[i][0], al[i][1], al[i][2], al[i][3],
                             bh2[j][0], bh2[j][1]);
                }
        }
    }

    // Epilogue: exp + mask + stores + per-row partial sums
#pragma unroll
    for (int i = 0; i < 4; i++) {
        const int rA = wm * 64 + i * 16 + lr;
        const int mGA = m0 + rA;
        const int mGB = mGA + 8;
        float rsA = 0.f, rsB = 0.f;
#pragma unroll
        for (int j = 0; j < 4; j++) {
            int col = j0 + wn * 32 + j * 8 + 2 * lq;
            float e0 = (masked && (col+0) > mGA) ? 0.f : __expf(acc[i][j][0] * SCALE_F);
            float e1 = (masked && (col+1) > mGA) ? 0.f : __expf(acc[i][j][1] * SCALE_F);
            float e2 = (masked && (col+0) > mGB) ? 0.f : __expf(acc[i][j][2] * SCALE_F);
            float e3 = (masked && (col+1) > mGB) ? 0.f : __expf(acc[i][j][3] * SCALE_F);
            rsA += e0 + e1; rsB += e2 + e3;
            float2 v0; v0.x = e0; v0.y = e1;
            float2 v1; v1.x = e2; v1.y = e3;
            *(float2*)(Pb + (size_t)mGA * NS + col) = v0;
            *(float2*)(Pb + (size_t)mGB * NS + col) = v1;
        }
        Srow[rA][wn * 4 + lq]     = rsA;
        Srow[rA + 8][wn * 4 + lq] = rsB;
    }
    __syncthreads();
    if (tid < 128) {
        float s = 0.f;
#pragma unroll
        for (int c = 0; c < 16; c++) s += Srow[tid][c];
        partial[((size_t)bh * NS + m0 + tid) * 16 + jblk] = s;
    }
}

// ---------------------------------------------------------------------------
__global__ __launch_bounds__(256)
void rowinv(const float* __restrict__ partial, float* __restrict__ inv)
{
    int r = blockIdx.x * 256 + threadIdx.x;
    const float4* p = (const float4*)(partial + (size_t)r * 16);
    float4 a = p[0], b = p[1], c = p[2], d = p[3];
    float s = (a.x + a.y + a.z + a.w) + (b.x + b.y + b.z + b.w)
            + (c.x + c.y + c.z + c.w) + (d.x + d.y + d.z + d.w);
    inv[r] = 1.f / s;
}

// ---------------------------------------------------------------------------
// O = softmax(P) @ V on tensor cores (tf32 mma.sync). Unchanged from R12 best.
// ---------------------------------------------------------------------------
__global__ __launch_bounds__(256)
void av_mma(float* __restrict__ P, const float* __restrict__ V,
            float* __restrict__ O, const float* __restrict__ inv,
            const int* __restrict__ use_mask)
{
    const int bh = blockIdx.y;
    const int m0 = ((int)gridDim.x - 1 - (int)blockIdx.x) * 128;
    const int tid = threadIdx.x;
    const int lane = tid & 31;
    const int warp = tid >> 5;
    const int wm = warp >> 1;            // 0..3
    const int wn = warp & 1;             // 0..1
    const bool masked = (*use_mask != 0);
    const int kmax = masked ? (m0 + 128) : NS;
    const int NT = kmax >> 5;

    __shared__ uint32_t Ps[2][32][132];  // [buf][k][m]
    __shared__ uint32_t Vs[2][32][68];   // [buf][k][n]
    __shared__ float sinv_s[128];

    float* Pb = P + (size_t)bh * NS * NS;
    const float* Vb = V + (size_t)bh * NS * HD;

    if (tid < 128) sinv_s[tid] = inv[(size_t)bh * NS + m0 + tid];

    const int pr0 = tid >> 3;            // 0..31
    const int pr1 = pr0 + 32;
    const int pr2 = pr0 + 64;
    const int pr3 = pr0 + 96;
    const int pkc = (tid & 7) << 2;
    const int vr0 = tid >> 4;            // 0..15  (k row)
    const int vr1 = vr0 + 16;
    const int vc  = (tid & 15) << 2;     // 0..60  (n col)

    float4 sp0, sp1, sp2, sp3, sv0, sv1;
    sp0 = *(const float4*)(Pb + (size_t)(m0 + pr0) * NS + pkc);
    sp1 = *(const float4*)(Pb + (size_t)(m0 + pr1) * NS + pkc);
    sp2 = *(const float4*)(Pb + (size_t)(m0 + pr2) * NS + pkc);
    sp3 = *(const float4*)(Pb + (size_t)(m0 + pr3) * NS + pkc);
    sv0 = *(const float4*)(Vb + (size_t)vr0 * HD + vc);
    sv1 = *(const float4*)(Vb + (size_t)vr1 * HD + vc);
    __syncthreads();                     // sinv_s visible
    {
        Ps[0][pkc+0][pr0] = f2tf32(sp0.x); Ps[0][pkc+1][pr0] = f2tf32(sp0.y);
        Ps[0][pkc+2][pr0] = f2tf32(sp0.z); Ps[0][pkc+3][pr0] = f2tf32(sp0.w);
        Ps[0][pkc+0][pr1] = f2tf32(sp1.x); Ps[0][pkc+1][pr1] = f2tf32(sp1.y);
        Ps[0][pkc+2][pr1] = f2tf32(sp1.z); Ps[0][pkc+3][pr1] = f2tf32(sp1.w);
        Ps[0][pkc+0][pr2] = f2tf32(sp2.x); Ps[0][pkc+1][pr2] = f2tf32(sp2.y);
        Ps[0][pkc+2][pr2] = f2tf32(sp2.z); Ps[0][pkc+3][pr2] = f2tf32(sp2.w);
        Ps[0][pkc+0][pr3] = f2tf32(sp3.x); Ps[0][pkc+1][pr3] = f2tf32(sp3.y);
        Ps[0][pkc+2][pr3] = f2tf32(sp3.z); Ps[0][pkc+3][pr3] = f2tf32(sp3.w);
        Vs[0][vr0][vc+0] = f2tf32(sv0.x); Vs[0][vr0][vc+1] = f2tf32(sv0.y);
        Vs[0][vr0][vc+2] = f2tf32(sv0.z); Vs[0][vr0][vc+3] = f2tf32(sv0.w);
        Vs[0][vr1][vc+0] = f2tf32(sv1.x); Vs[0][vr1][vc+1] = f2tf32(sv1.y);
        Vs[0][vr1][vc+2] = f2tf32(sv1.z); Vs[0][vr1][vc+3] = f2tf32(sv1.w);
        float s0 = sinv_s[pr0], s1 = sinv_s[pr1], s2 = sinv_s[pr2], s3 = sinv_s[pr3];
        float4 w;
        w.x = sp0.x*s0; w.y = sp0.y*s0; w.z = sp0.z*s0; w.w = sp0.w*s0;
        *(float4*)(Pb + (size_t)(m0 + pr0) * NS + pkc) = w;
        w.x = sp1.x*s1; w.y = sp1.y*s1; w.z = sp1.z*s1; w.w = sp1.w*s1;
        *(float4*)(Pb + (size_t)(m0 + pr1) * NS + pkc) = w;
        w.x = sp2.x*s2; w.y = sp2.y*s2; w.z = sp2.z*s2; w.w = sp2.w*s2;
        *(float4*)(Pb + (size_t)(m0 + pr2) * NS + pkc) = w;
        w.x = sp3.x*s3; w.y = sp3.y*s3; w.z = sp3.z*s3; w.w = sp3.w*s3;
        *(float4*)(Pb + (size_t)(m0 + pr3) * NS + pkc) = w;
    }

    float acc[2][4][4];
#pragma unroll
    for (int i = 0; i < 2; i++)
#pragma unroll
        for (int j = 0; j < 4; j++)
#pragma unroll
            for (int c = 0; c < 4; c++) acc[i][j][c] = 0.f;

    const int lq = lane & 3;
    const int lr = lane >> 2;

    for (int t = 0; t < NT; t++) {
        __syncthreads();
        if (t + 1 < NT) {
            int kk0 = (t + 1) * 32;
            sp0 = *(const float4*)(Pb + (size_t)(m0 + pr0) * NS + kk0 + pkc);
            sp1 = *(const float4*)(Pb + (size_t)(m0 + pr1) * NS + kk0 + pkc);
            sp2 = *(const float4*)(Pb + (size_t)(m0 + pr2) * NS + kk0 + pkc);
            sp3 = *(const float4*)(Pb + (size_t)(m0 + pr3) * NS + kk0 + pkc);
            sv0 = *(const float4*)(Vb + (size_t)(kk0 + vr0) * HD + vc);
            sv1 = *(const float4*)(Vb + (size_t)(kk0 + vr1) * HD + vc);
        }
        const int cb = t & 1;
#pragma unroll
        for (int ks = 0; ks < 4; ks++) {
            const int kb = ks * 8;
            uint32_t af[2][4], bf[4][2];
#pragma unroll
            for (int i = 0; i < 2; i++) {
                int m = wm * 32 + i * 16 + lr;
                af[i][0] = Ps[cb][kb + lq    ][m];
                af[i][1] = Ps[cb][kb + lq    ][m + 8];
                af[i][2] = Ps[cb][kb + lq + 4][m];
                af[i][3] = Ps[cb][kb + lq + 4][m + 8];
            }
#pragma unroll
            for (int j = 0; j < 4; j++) {
                int n = wn * 32 + j * 8 + lr;
                bf[j][0] = Vs[cb][kb + lq    ][n];
                bf[j][1] = Vs[cb][kb + lq + 4][n];
            }
#pragma unroll
            for (int i = 0; i < 2; i++)
#pragma unroll
                for (int j = 0; j < 4; j++)
                    mma_tf32(acc[i][j][0], acc[i][j][1], acc[i][j][2], acc[i][j][3],
                             af[i][0], af[i][1], af[i][2], af[i][3],
                             bf[j][0], bf[j][1]);
        }
        if (t + 1 < NT) {
            const int nb = (t + 1) & 1;
            const int kk0 = (t + 1) * 32;
            Ps[nb][pkc+0][pr0] = f2tf32(sp0.x); Ps[nb][pkc+1][pr0] = f2tf32(sp0.y);
            Ps[nb][pkc+2][pr0] = f2tf32(sp0.z); Ps[nb][pkc+3][pr0] = f2tf32(sp0.w);
            Ps[nb][pkc+0][pr1] = f2tf32(sp1.x); Ps[nb][pkc+1][pr1] = f2tf32(sp1.y);
            Ps[nb][pkc+2][pr1] = f2tf32(sp1.z); Ps[nb][pkc+3][pr1] = f2tf32(sp1.w);
            Ps[nb][pkc+0][pr2] = f2tf32(sp2.x); Ps[nb][pkc+1][pr2] = f2tf32(sp2.y);
            Ps[nb][pkc+2][pr2] = f2tf32(sp2.z); Ps[nb][pkc+3][pr2] = f2tf32(sp2.w);
            Ps[nb][pkc+0][pr3] = f2tf32(sp3.x); Ps[nb][pkc+1][pr3] = f2tf32(sp3.y);
            Ps[nb][pkc+2][pr3] = f2tf32(sp3.z); Ps[nb][pkc+3][pr3] = f2tf32(sp3.w);
            Vs[nb][vr0][vc+0] = f2tf32(sv0.x); Vs[nb][vr0][vc+1] = f2tf32(sv0.y);
            Vs[nb][vr0][vc+2] = f2tf32(sv0.z); Vs[nb][vr0][vc+3] = f2tf32(sv0.w);
            Vs[nb][vr1][vc+0] = f2tf32(sv1.x); Vs[nb][vr1][vc+1] = f2tf32(sv1.y);
            Vs[nb][vr1][vc+2] = f2tf32(sv1.z); Vs[nb][vr1][vc+3] = f2tf32(sv1.w);
            float s0 = sinv_s[pr0], s1 = sinv_s[pr1], s2 = sinv_s[pr2], s3 = sinv_s[pr3];
            float4 w;
            w.x = sp0.x*s0; w.y = sp0.y*s0; w.z = sp0.z*s0; w.w = sp0.w*s0;
            *(float4*)(Pb + (size_t)(m0 + pr0) * NS + kk0 + pkc) = w;
            w.x = sp1.x*s1; w.y = sp1.y*s1; w.z = sp1.z*s1; w.w = sp1.w*s1;
            *(float4*)(Pb + (size_t)(m0 + pr1) * NS + kk0 + pkc) = w;
            w.x = sp2.x*s2; w.y = sp2.y*s2; w.z = sp2.z*s2; w.w = sp2.w*s2;
            *(float4*)(Pb + (size_t)(m0 + pr2) * NS + kk0 + pkc) = w;
            w.x = sp3.x*s3; w.y = sp3.y*s3; w.z = sp3.z*s3; w.w = sp3.w*s3;
            *(float4*)(Pb + (size_t)(m0 + pr3) * NS + kk0 + pkc) = w;
        }
    }

#pragma unroll
    for (int i = 0; i < 2; i++) {
#pragma unroll
        for (int j = 0; j < 4; j++) {
            int col = wn * 32 + j * 8 + 2 * lq;
            int lmA = wm * 32 + i * 16 + lr;
            int lmB = lmA + 8;
            float sA = sinv_s[lmA], sB = sinv_s[lmB];
            float2 v0, v1;
            v0.x = acc[i][j][0] * sA; v0.y = acc[i][j][1] * sA;
            v1.x = acc[i][j][2] * sB; v1.y = acc[i][j][3] * sB;
            *(float2*)(O + ((size_t)bh * NS + m0 + lmA) * HD + col) = v0;
            *(float2*)(O + ((size_t)bh * NS + m0 + lmB) * HD + col) = v1;
        }
    }
}

// ---------------------------------------------------------------------------
extern "C" void kernel_launch(void* const* d_in, const int* in_sizes, int n_in,
                              void* d_out, int out_size)
{
    const float* q      = (const float*)d_in[0];
    const float* k      = (const float*)d_in[1];
    const float* v      = (const float*)d_in[2];
    const float* qkv_w  = (const float*)d_in[3];
    const float* proj_w = (const float*)d_in[4];
    const float* proj_b = (const float*)d_in[5];
    const int*   use_mask = (const int*)d_in[6];

    float* out      = (float*)d_out;
    float* x_out    = out;                       // (B, N, C)
    float* attn_out = out + (size_t)XSIZE;       // (B, H, N, N)

    float *qh, *kh, *vh, *ao, *part, *invs;
    cudaGetSymbolAddress((void**)&qh, g_qh);
    cudaGetSymbolAddress((void**)&kh, g_kh);
    cudaGetSymbolAddress((void**)&vh, g_vh);
    cudaGetSymbolAddress((void**)&ao, g_ao);
    cudaGetSymbolAddress((void**)&part, g_partial);
    cudaGetSymbolAddress((void**)&invs, g_inv);

    dim3 blk(256);

    // QKV projections on tensor cores (mma.sync tf32), head-transposed outputs
    mma_mm<0><<<dim3(CD/128, (BB*NS)/128, 3), blk>>>(q, k, v, qkv_w, qh, kh, vh, nullptr);

    // exp(scale * Q K^T) with mask on tensor cores (3xTF32) + partial sums
    score_mma<<<dim3(NS/128, NS/128, BB*HH), blk>>>(qh, kh, attn_out, part, use_mask);

    // Row inverse sums
    rowinv<<<(BB*HH*NS)/256, blk>>>(part, invs);

    // Normalize P (finalizing attn output) + P @ V on tensor cores
    av_mma<<<dim3(NS/128, BB*HH), blk>>>(attn_out, vh, ao, invs, use_mask);

    // Output projection + bias on tensor cores
    mma_mm<1><<<dim3(CD/128, (BB*NS)/128, 1), blk>>>(ao, nullptr, nullptr, proj_w,
                                                     x_out, nullptr, nullptr, proj_b);
}